// round 9
// baseline (speedup 1.0000x reference)
#include <cuda_runtime.h>
#include <cuda_fp16.h>
#include <math.h>
#include <stdint.h>

// ---------------- problem constants ----------------
#define NBATCH 4096
#define NTOK   64
#define MTOT   (NBATCH * NTOK)
#define DOBS   128
#define NTILE  (MTOT / 128)        // 2048

// ---------------- packed fp16 weight fragments ----------------
#define PH_E1  0
#define PH_E2  4096
#define PH_QK  6144
#define PH_I2  9216
#define PH_I1  17408
#define PH_TOT 29696
__device__ uint2  g_packh[PH_TOT];
__device__ float  g_bc[256];
// activation images: [tile][chunk][128][40] fp16  (32 data cols + 8 pad)
#define CH_FP16 5120                       // 128*40
__device__ __half g_obs_img[(size_t)NTILE * 4 * CH_FP16];
__device__ __half g_h_img[(size_t)NTILE * 4 * CH_FP16];
__device__ __half g_msgs_img[(size_t)NTILE * 2 * CH_FP16];
__device__ __half g_ctx_img[(size_t)NTILE * 2 * CH_FP16];
__device__ __half g_z_img[(size_t)NTILE * 8 * CH_FP16];
__device__ float  g_qkv[(size_t)MTOT * 192];
__device__ float  g_msgs_s[(size_t)MTOT * 64];

// ---------------- helpers ----------------
__device__ __forceinline__ uint32_t smem_u32(const void* p) {
    uint32_t a;
    asm("{ .reg .u64 t; cvta.to.shared.u64 t, %1; cvt.u32.u64 %0, t; }" : "=r"(a) : "l"(p));
    return a;
}
#define MBAR_INIT(mb, c) \
    asm volatile("mbarrier.init.shared.b64 [%0], %1;" :: "r"(mb), "r"((uint32_t)(c)) : "memory")
#define MBAR_EXPECT(mb, tx) \
    asm volatile("mbarrier.arrive.expect_tx.shared.b64 _, [%0], %1;" :: "r"(mb), "r"((uint32_t)(tx)) : "memory")
#define BULK_G2S(dst, src, bytes, mb) \
    asm volatile("cp.async.bulk.shared::cta.global.mbarrier::complete_tx::bytes [%0], [%1], %2, [%3];" \
                 :: "r"(dst), "l"(src), "r"((uint32_t)(bytes)), "r"(mb) : "memory")
#define MBAR_WAIT(mb, ph) do {                                                      \
    uint32_t _m = (mb), _p = (uint32_t)(ph), _d;                                    \
    asm volatile("{\n\t.reg .pred p;\n\t"                                           \
        "mbarrier.try_wait.parity.acquire.cta.shared::cta.b64 p, [%1], %2;\n\t"     \
        "selp.b32 %0, 1, 0, p;\n\t}" : "=r"(_d) : "r"(_m), "r"(_p) : "memory");     \
    if (!_d) {                                                                      \
        asm volatile("{\n\t.reg .pred P1;\n\t"                                      \
            "WL_%=:\n\t"                                                            \
            "mbarrier.try_wait.parity.acquire.cta.shared::cta.b64 P1, [%0], %1, 0x989680;\n\t" \
            "@P1 bra.uni WD_%=;\n\tbra.uni WL_%=;\n\tWD_%=:\n\t}"                   \
            :: "r"(_m), "r"(_p) : "memory");                                        \
    } } while (0)

#define MMA_F16(acc, a, bx, by)                                                      \
    asm volatile("mma.sync.aligned.m16n8k16.row.col.f32.f16.f16.f32 "                \
                 "{%0,%1,%2,%3}, {%4,%5,%6,%7}, {%8,%9}, {%0,%1,%2,%3};"             \
                 : "+f"((acc)[0]), "+f"((acc)[1]), "+f"((acc)[2]), "+f"((acc)[3])    \
                 : "r"((a)[0]), "r"((a)[1]), "r"((a)[2]), "r"((a)[3]),               \
                   "r"(bx), "r"(by))

__device__ __forceinline__ uint32_t h2u(__half2 h) { return *reinterpret_cast<uint32_t*>(&h); }

// ---------------- obs -> fp16 image ----------------
__global__ void conv_img(const float* __restrict__ s, __half* __restrict__ img)
{
    int gid = blockIdx.x * blockDim.x + threadIdx.x;
    if (gid >= MTOT * 16) return;
    const int r = gid >> 4, q = gid & 15;
    float4 v0 = *(const float4*)(s + (size_t)r * 128 + q * 8);
    float4 v1 = *(const float4*)(s + (size_t)r * 128 + q * 8 + 4);
    uint4 o;
    o.x = h2u(__floats2half2_rn(v0.x, v0.y));
    o.y = h2u(__floats2half2_rn(v0.z, v0.w));
    o.z = h2u(__floats2half2_rn(v1.x, v1.y));
    o.w = h2u(__floats2half2_rn(v1.z, v1.w));
    const size_t a = ((size_t)((r >> 7) * 4 + (q >> 2)) * 128 + (r & 127)) * 40 + (q & 3) * 8;
    *(uint4*)(img + a) = o;
}

// ---------------- single prep kernel: fold + pack fp16 fragments ----------------
__device__ __forceinline__ float wcomb_elem(int k, int n,
                                            const float* __restrict__ out_w,
                                            const float* __restrict__ int_w1)
{
    if (k < 128) return int_w1[(size_t)k * 256 + n];
    const int c = k - 128;
    float s = 0.f;
#pragma unroll 4
    for (int m = 0; m < 64; m++)
        s = fmaf(out_w[c * 64 + m], int_w1[(size_t)(128 + m) * 256 + n], s);
    return s;
}

__global__ void pack_all(const float* __restrict__ enc_w1, const float* __restrict__ enc_w2,
                         const float* __restrict__ inp_w,  const float* __restrict__ out_w,
                         const float* __restrict__ out_b,  const float* __restrict__ int_w1,
                         const float* __restrict__ int_b1, const float* __restrict__ int_w2)
{
    const int gid = blockIdx.x * blockDim.x + threadIdx.x;
    int p, N = 0;
    const float* W = nullptr;
    uint2* dst = nullptr;
    bool i1 = false;
    if (gid < 4096)        { p = gid;         W = enc_w1; dst = g_packh + PH_E1; N = 128; }
    else if (gid < 6144)   { p = gid - 4096;  W = enc_w2; dst = g_packh + PH_E2; N = 64;  }
    else if (gid < 9216)   { p = gid - 6144;  W = inp_w;  dst = g_packh + PH_QK; N = 192; }
    else if (gid < 17408)  { p = gid - 9216;  W = int_w2; dst = g_packh + PH_I2; N = 128; }
    else if (gid < 29696)  { p = gid - 17408; dst = g_packh + PH_I1; N = 256; i1 = true; }
    else if (gid < 29952) {
        const int n = gid - 29696;
        float s = int_b1[n];
        for (int m = 0; m < 64; m++) s = fmaf(out_b[m], int_w1[(size_t)(128 + m) * 256 + n], s);
        g_bc[n] = s;
        return;
    } else return;

    const int lane = p & 31;
    const int tile = p >> 5;
    const int nt = N >> 3;
    const int j = tile % nt, kk = tile / nt;
    const int t = lane & 3, g = lane >> 2;
    const int k0 = kk * 16, n = j * 8 + g;
    float w0, w1, w2, w3;
    if (i1) {
        w0 = wcomb_elem(k0 + 2 * t,     n, out_w, int_w1);
        w1 = wcomb_elem(k0 + 2 * t + 1, n, out_w, int_w1);
        w2 = wcomb_elem(k0 + 2 * t + 8, n, out_w, int_w1);
        w3 = wcomb_elem(k0 + 2 * t + 9, n, out_w, int_w1);
    } else {
        w0 = W[(size_t)(k0 + 2 * t) * N + n];
        w1 = W[(size_t)(k0 + 2 * t + 1) * N + n];
        w2 = W[(size_t)(k0 + 2 * t + 8) * N + n];
        w3 = W[(size_t)(k0 + 2 * t + 9) * N + n];
    }
    uint2 v;
    v.x = h2u(__floats2half2_rn(w0, w1));
    v.y = h2u(__floats2half2_rn(w2, w3));
    dst[p] = v;
}

// ---------------- bulk-fed fp16 GEMM, 128 rows/CTA, 512 threads ----------------
// A from padded tiled image(s): img0 first NCH0 chunks, img1 the rest.
// MODE: 0 none, 1 relu, 2 LayerNorm+relu.  W16: 0 fp32 out; 1 fp16 img out; 2 both.
#define AW0 784                       // smem word offset of A image

template<int K, int N, int NCH0, int MODE, int W16>
__global__ void __launch_bounds__(512)
g4(const __half* __restrict__ img0, const __half* __restrict__ img1,
   const uint2* __restrict__ packB, const float* __restrict__ bias,
   const float* __restrict__ lng, const float* __restrict__ lnb,
   float* __restrict__ out, __half* __restrict__ out16)
{
    extern __shared__ float sm[];
    constexpr int NCH = K / 32, NT = N / 32;
    constexpr int SBW = N * 16;                 // B stage words
    constexpr int BW0 = AW0 + NCH * 2560;       // B base (words)
    constexpr int RW0 = BW0;                    // reduce scratch reuses B after mainloop
    const int tid = threadIdx.x;
    const int m0 = blockIdx.x * 128;
    const uint32_t sbase = smem_u32(sm);
    const uint32_t mb0 = sbase + 768 * 4;
    const uint32_t mb1 = sbase + 772 * 4;

    for (int i = tid; i < N; i += 512) sm[i] = bias[i];
    if (MODE == 2)
        for (int i = tid; i < N; i += 512) { sm[256 + i] = lng[i]; sm[512 + i] = lnb[i]; }
    if (tid == 0) { MBAR_INIT(mb0, 1); MBAR_INIT(mb1, 1); }
    __syncthreads();

    if (tid == 0) {
        MBAR_EXPECT(mb0, NCH * 10240 + N * 64);
        BULK_G2S(sbase + AW0 * 4, img0 + (size_t)blockIdx.x * NCH0 * CH_FP16,
                 NCH0 * 10240, mb0);
        if (NCH0 < NCH)
            BULK_G2S(sbase + (AW0 + NCH0 * 2560) * 4,
                     img1 + (size_t)blockIdx.x * (NCH - NCH0) * CH_FP16,
                     (NCH - NCH0) * 10240, mb0);
        BULK_G2S(sbase + BW0 * 4, (const char*)packB, N * 64, mb0);
        if (NCH > 1) {
            MBAR_EXPECT(mb1, N * 64);
            BULK_G2S(sbase + (BW0 + SBW) * 4, (const char*)packB + N * 64, N * 64, mb1);
        }
    }

    const int lane = tid & 31, w = tid >> 5;
    const int wr = w >> 2, wc = w & 3;
    const int t = lane & 3, g = lane >> 2;
    const int r0 = wr * 32;

    float acc[2][NT][4];
#pragma unroll
    for (int mt = 0; mt < 2; mt++)
#pragma unroll
        for (int j = 0; j < NT; j++)
            acc[mt][j][0] = acc[mt][j][1] = acc[mt][j][2] = acc[mt][j][3] = 0.f;

#pragma unroll 1
    for (int c = 0; c < NCH; c++) {
        MBAR_WAIT((c & 1) ? mb1 : mb0, (c >> 1) & 1);
        const uint32_t* sw = (const uint32_t*)(sm + AW0 + c * 2560);
        const uint2*    sB = (const uint2*)(sm + BW0 + (c & 1) * SBW);
#pragma unroll
        for (int kk2 = 0; kk2 < 2; kk2++) {
            uint32_t a[2][4];
#pragma unroll
            for (int mt = 0; mt < 2; mt++) {
                const int rb = r0 + mt * 16 + g;
                const int b0 = rb * 20 + kk2 * 8;
                const int b1 = (rb + 8) * 20 + kk2 * 8;
                a[mt][0] = sw[b0 + t];
                a[mt][1] = sw[b1 + t];
                a[mt][2] = sw[b0 + t + 4];
                a[mt][3] = sw[b1 + t + 4];
            }
#pragma unroll
            for (int j = 0; j < NT; j++) {
                const uint2 bv = sB[(size_t)(kk2 * (N / 8) + wc * NT + j) * 32 + lane];
#pragma unroll
                for (int mt = 0; mt < 2; mt++)
                    MMA_F16(acc[mt][j], a[mt], bv.x, bv.y);
            }
        }
        __syncthreads();
        if (c + 2 < NCH && tid == 0) {
            const uint32_t mb = (c & 1) ? mb1 : mb0;
            MBAR_EXPECT(mb, N * 64);
            BULK_G2S(sbase + (BW0 + (c & 1) * SBW) * 4,
                     (const char*)packB + (size_t)(c + 2) * N * 64, N * 64, mb);
        }
    }

    // ---------------- epilogue ----------------
    auto store_pair = [&](int mt, int j, float v0, float v1, float v2, float v3) {
        const int n0 = wc * (N / 4) + j * 8 + 2 * t;
        const int rl = r0 + mt * 16 + g;
        if (W16 >= 1) {
            const size_t base = ((size_t)blockIdx.x * (N / 32) + (n0 >> 5)) * CH_FP16 + (n0 & 31);
            *(__half2*)(out16 + base + (size_t)rl * 40)       = __floats2half2_rn(v0, v1);
            *(__half2*)(out16 + base + (size_t)(rl + 8) * 40) = __floats2half2_rn(v2, v3);
        }
        if (W16 != 1) {
            *(float2*)(out + (size_t)(m0 + rl) * N + n0)     = make_float2(v0, v1);
            *(float2*)(out + (size_t)(m0 + rl + 8) * N + n0) = make_float2(v2, v3);
        }
    };

    if (MODE == 2) {
#pragma unroll
        for (int mt = 0; mt < 2; mt++)
#pragma unroll
            for (int j = 0; j < NT; j++) {
                const int n0 = wc * (N / 4) + j * 8 + 2 * t;
                acc[mt][j][0] += sm[n0]; acc[mt][j][1] += sm[n0 + 1];
                acc[mt][j][2] += sm[n0]; acc[mt][j][3] += sm[n0 + 1];
            }
        float ps[2][2] = {{0,0},{0,0}}, pq[2][2] = {{0,0},{0,0}};
#pragma unroll
        for (int mt = 0; mt < 2; mt++)
#pragma unroll
            for (int j = 0; j < NT; j++) {
                ps[mt][0] += acc[mt][j][0] + acc[mt][j][1];
                pq[mt][0] += acc[mt][j][0] * acc[mt][j][0] + acc[mt][j][1] * acc[mt][j][1];
                ps[mt][1] += acc[mt][j][2] + acc[mt][j][3];
                pq[mt][1] += acc[mt][j][2] * acc[mt][j][2] + acc[mt][j][3] * acc[mt][j][3];
            }
#pragma unroll
        for (int mt = 0; mt < 2; mt++)
#pragma unroll
            for (int h = 0; h < 2; h++) {
                ps[mt][h] += __shfl_xor_sync(0xffffffffu, ps[mt][h], 1);
                ps[mt][h] += __shfl_xor_sync(0xffffffffu, ps[mt][h], 2);
                pq[mt][h] += __shfl_xor_sync(0xffffffffu, pq[mt][h], 1);
                pq[mt][h] += __shfl_xor_sync(0xffffffffu, pq[mt][h], 2);
            }
        if (t == 0) {
#pragma unroll
            for (int mt = 0; mt < 2; mt++)
#pragma unroll
                for (int h = 0; h < 2; h++) {
                    const int rl = r0 + mt * 16 + g + 8 * h;
                    sm[RW0 + rl * 4 + wc]       = ps[mt][h];
                    sm[RW0 + 512 + rl * 4 + wc] = pq[mt][h];
                }
        }
        __syncthreads();
        float mu[2][2], rs[2][2];
#pragma unroll
        for (int mt = 0; mt < 2; mt++)
#pragma unroll
            for (int h = 0; h < 2; h++) {
                const int rl = r0 + mt * 16 + g + 8 * h;
                const float s_ = sm[RW0 + rl * 4] + sm[RW0 + rl * 4 + 1]
                               + sm[RW0 + rl * 4 + 2] + sm[RW0 + rl * 4 + 3];
                const float q_ = sm[RW0 + 512 + rl * 4] + sm[RW0 + 512 + rl * 4 + 1]
                               + sm[RW0 + 512 + rl * 4 + 2] + sm[RW0 + 512 + rl * 4 + 3];
                const float m_ = s_ * (1.f / N);
                const float v_ = q_ * (1.f / N) - m_ * m_;
                mu[mt][h] = m_;
                rs[mt][h] = rsqrtf(v_ + 1e-5f);
            }
#pragma unroll
        for (int mt = 0; mt < 2; mt++)
#pragma unroll
            for (int j = 0; j < NT; j++) {
                const int n0 = wc * (N / 4) + j * 8 + 2 * t;
                const float g0 = sm[256 + n0], g1 = sm[256 + n0 + 1];
                const float b0 = sm[512 + n0], b1 = sm[512 + n0 + 1];
                store_pair(mt, j,
                    fmaxf((acc[mt][j][0] - mu[mt][0]) * rs[mt][0] * g0 + b0, 0.f),
                    fmaxf((acc[mt][j][1] - mu[mt][0]) * rs[mt][0] * g1 + b1, 0.f),
                    fmaxf((acc[mt][j][2] - mu[mt][1]) * rs[mt][1] * g0 + b0, 0.f),
                    fmaxf((acc[mt][j][3] - mu[mt][1]) * rs[mt][1] * g1 + b1, 0.f));
            }
    } else {
#pragma unroll
        for (int mt = 0; mt < 2; mt++)
#pragma unroll
            for (int j = 0; j < NT; j++) {
                const int n0 = wc * (N / 4) + j * 8 + 2 * t;
                const float b0 = sm[n0], b1 = sm[n0 + 1];
                float v0 = acc[mt][j][0] + b0, v1 = acc[mt][j][1] + b1;
                float v2 = acc[mt][j][2] + b0, v3 = acc[mt][j][3] + b1;
                if (MODE == 1) {
                    v0 = fmaxf(v0, 0.f); v1 = fmaxf(v1, 0.f);
                    v2 = fmaxf(v2, 0.f); v3 = fmaxf(v3, 0.f);
                }
                store_pair(mt, j, v0, v1, v2, v3);
            }
    }
}

// ---------------- attention (scalar fp32; ctx -> fp16 image) ----------------
#define LD_QKV 196
#define LD_CTX 68
__global__ void __launch_bounds__(256)
attn_kernel(const float* __restrict__ qkv, __half* __restrict__ ctx_img)
{
    extern __shared__ float smA[];
    float* sQ = smA;
    float* sC = smA + 64 * LD_QKV;
    const int b = blockIdx.x, tid = threadIdx.x;
    const float* src = qkv + (size_t)b * 64 * 192;
    for (int i = tid; i < 64 * 192 / 4; i += 256) {
        int r = i / 48, c4 = i - r * 48;
        *(float4*)(sQ + r * LD_QKV + c4 * 4) = *(const float4*)(src + r * 192 + c4 * 4);
    }
    __syncthreads();
    {
        const int h = tid >> 6, q = tid & 63;
        float qv[16];
#pragma unroll
        for (int d = 0; d < 16; d++) qv[d] = sQ[q * LD_QKV + h * 16 + d];
        float m = -1e30f;
#pragma unroll 4
        for (int k = 0; k < 64; k++) {
            const float* kp = sQ + k * LD_QKV + 64 + h * 16;
            float s = 0.f;
#pragma unroll
            for (int d = 0; d < 16; d++) s = fmaf(qv[d], kp[d], s);
            m = fmaxf(m, s * 0.25f);
        }
        float ssum = 0.f, ctx[16];
#pragma unroll
        for (int d = 0; d < 16; d++) ctx[d] = 0.f;
#pragma unroll 2
        for (int k = 0; k < 64; k++) {
            const float* kp = sQ + k * LD_QKV + 64 + h * 16;
            float s = 0.f;
#pragma unroll
            for (int d = 0; d < 16; d++) s = fmaf(qv[d], kp[d], s);
            float p = __expf(fmaf(s, 0.25f, -m));
            ssum += p;
            const float* vp = sQ + k * LD_QKV + 128 + h * 16;
#pragma unroll
            for (int d = 0; d < 16; d++) ctx[d] = fmaf(p, vp[d], ctx[d]);
        }
        float inv = 1.f / ssum;
#pragma unroll
        for (int d = 0; d < 16; d++) sC[q * LD_CTX + h * 16 + d] = ctx[d] * inv;
    }
    __syncthreads();
    // ctx -> padded image; tile = b/2, rows (b&1)*64..
    const int tile = b >> 1, rb = (b & 1) * 64;
    for (int i = tid; i < 64 * 64; i += 256) {
        const int r = i >> 6, c = i & 63;
        ctx_img[((size_t)(tile * 2 + (c >> 5)) * 128 + rb + r) * 40 + (c & 31)] =
            __float2half_rn(sC[r * LD_CTX + c]);
    }
}

// ---------------- launch ----------------
extern "C" void kernel_launch(void* const* d_in, const int* in_sizes, int n_in,
                              void* d_out, int out_size)
{
    const float* obs    = (const float*)d_in[0];
    const float* enc_w1 = (const float*)d_in[1];
    const float* enc_b1 = (const float*)d_in[2];
    const float* enc_w2 = (const float*)d_in[3];
    const float* enc_b2 = (const float*)d_in[4];
    const float* inp_w  = (const float*)d_in[5];
    const float* inp_b  = (const float*)d_in[6];
    const float* out_w  = (const float*)d_in[7];
    const float* out_b  = (const float*)d_in[8];
    const float* int_w1 = (const float*)d_in[9];
    const float* int_b1 = (const float*)d_in[10];
    const float* ln_g   = (const float*)d_in[11];
    const float* ln_b   = (const float*)d_in[12];
    const float* int_w2 = (const float*)d_in[13];
    const float* int_b2 = (const float*)d_in[14];

    float* outE = (float*)d_out;
    const size_t esz = (size_t)MTOT * DOBS;
    float* outM = ((size_t)out_size > esz) ? outE + esz : nullptr;

    uint2* p_pack;
    float *p_bc, *p_qkv, *p_msgs;
    __half *p_obs_i, *p_h_i, *p_msgs_i, *p_ctx_i, *p_z_i;
    cudaGetSymbolAddress((void**)&p_pack,  g_packh);
    cudaGetSymbolAddress((void**)&p_bc,    g_bc);
    cudaGetSymbolAddress((void**)&p_obs_i, g_obs_img);
    cudaGetSymbolAddress((void**)&p_h_i,   g_h_img);
    cudaGetSymbolAddress((void**)&p_msgs_i, g_msgs_img);
    cudaGetSymbolAddress((void**)&p_ctx_i, g_ctx_img);
    cudaGetSymbolAddress((void**)&p_z_i,   g_z_img);
    cudaGetSymbolAddress((void**)&p_qkv,   g_qkv);
    cudaGetSymbolAddress((void**)&p_msgs,  g_msgs_s);
    float* msgs = outM ? outM : p_msgs;

    auto smB = [](int K, int N) { return (784 + (K / 32) * 2560 + 2 * N * 16) * 4; };
    const int sm_e1 = smB(128, 128);
    const int sm_e2 = smB(128, 64);
    const int sm_qk = smB(64, 192);
    const int sm_i1 = smB(192, 256);
    const int sm_i2 = smB(256, 128);
    const int sm_at = (64 * LD_QKV + 64 * LD_CTX) * 4;

    cudaFuncSetAttribute((g4<128, 128, 4, 1, 1>), cudaFuncAttributeMaxDynamicSharedMemorySize, sm_e1);
    cudaFuncSetAttribute((g4<128, 64, 4, 0, 2>),  cudaFuncAttributeMaxDynamicSharedMemorySize, sm_e2);
    cudaFuncSetAttribute((g4<64, 192, 2, 0, 0>),  cudaFuncAttributeMaxDynamicSharedMemorySize, sm_qk);
    cudaFuncSetAttribute((g4<192, 256, 4, 2, 1>), cudaFuncAttributeMaxDynamicSharedMemorySize, sm_i1);
    cudaFuncSetAttribute((g4<256, 128, 8, 0, 0>), cudaFuncAttributeMaxDynamicSharedMemorySize, sm_i2);
    cudaFuncSetAttribute(attn_kernel, cudaFuncAttributeMaxDynamicSharedMemorySize, sm_at);

    pack_all<<<(29952 + 255) / 256, 256>>>(enc_w1, enc_w2, inp_w, out_w, out_b,
                                           int_w1, int_b1, int_w2);
    conv_img<<<(MTOT * 16 + 511) / 512, 512>>>(obs, p_obs_i);

    const int G = NTILE;  // 2048

    // enc1: h_img = relu(obs @ W1 + b1)
    g4<128, 128, 4, 1, 1><<<G, 512, sm_e1>>>(p_obs_i, nullptr, p_pack + PH_E1,
                                             enc_b1, nullptr, nullptr, nullptr, p_h_i);
    // enc2: msgs (fp32 out) + msgs_img
    g4<128, 64, 4, 0, 2><<<G, 512, sm_e2>>>(p_h_i, nullptr, p_pack + PH_E2,
                                            enc_b2, nullptr, nullptr, msgs, p_msgs_i);
    // qkv (fp32 for scalar attention)
    g4<64, 192, 2, 0, 0><<<G, 512, sm_qk>>>(p_msgs_i, nullptr, p_pack + PH_QK,
                                            inp_b, nullptr, nullptr, p_qkv, nullptr);
    // attention -> ctx image
    attn_kernel<<<NBATCH, 256, sm_at>>>(p_qkv, p_ctx_i);
    // int1 (out-proj folded): z_img = LN+relu([obs|ctx] @ Wcomb + bc)
    g4<192, 256, 4, 2, 1><<<G, 512, sm_i1>>>(p_obs_i, p_ctx_i, p_pack + PH_I1,
                                             p_bc, ln_g, ln_b, nullptr, p_z_i);
    // int2: enriched = z @ W2' + b2'
    g4<256, 128, 8, 0, 0><<<G, 512, sm_i2>>>(p_z_i, nullptr, p_pack + PH_I2,
                                             int_b2, nullptr, nullptr, outE, nullptr);
}

// round 10
// speedup vs baseline: 1.1294x; 1.1294x over previous
#include <cuda_runtime.h>
#include <cuda_fp16.h>
#include <math.h>
#include <stdint.h>

// ---------------- problem constants ----------------
#define NBATCH 4096
#define NTOK   64
#define MTOT   (NBATCH * NTOK)
#define DOBS   128
#define NTILE  (MTOT / 128)        // 2048
#define CH_H   5120                // halves per image chunk (128 rows x 40)

// ---------------- packed fp16 weight fragments ----------------
#define PH_E1  0
#define PH_E2  4096
#define PH_QK  6144
#define PH_I2  9216
#define PH_I1  17408
#define PH_TOT 29696
__device__ uint2  g_packh[PH_TOT];
__device__ float  g_bc[256];
__device__ __half g_obs_img[(size_t)NTILE * 4 * CH_H];
__device__ __half g_msgs_img[(size_t)NTILE * 2 * CH_H];
__device__ __half g_ctx_img[(size_t)NTILE * 2 * CH_H];
__device__ __half g_z_img[(size_t)NTILE * 8 * CH_H];
__device__ float  g_msgs_s[(size_t)MTOT * 64];

// ---------------- helpers ----------------
__device__ __forceinline__ uint32_t smem_u32(const void* p) {
    uint32_t a;
    asm("{ .reg .u64 t; cvta.to.shared.u64 t, %1; cvt.u32.u64 %0, t; }" : "=r"(a) : "l"(p));
    return a;
}
#define MBAR_INIT(mb, c) \
    asm volatile("mbarrier.init.shared.b64 [%0], %1;" :: "r"(mb), "r"((uint32_t)(c)) : "memory")
#define MBAR_EXPECT(mb, tx) \
    asm volatile("mbarrier.arrive.expect_tx.shared.b64 _, [%0], %1;" :: "r"(mb), "r"((uint32_t)(tx)) : "memory")
#define BULK_G2S(dst, src, bytes, mb) \
    asm volatile("cp.async.bulk.shared::cta.global.mbarrier::complete_tx::bytes [%0], [%1], %2, [%3];" \
                 :: "r"(dst), "l"(src), "r"((uint32_t)(bytes)), "r"(mb) : "memory")
#define BULK_S2G(gdst, ssrc, bytes) \
    asm volatile("cp.async.bulk.global.shared::cta.bulk_group [%0], [%1], %2;" \
                 :: "l"(gdst), "r"(ssrc), "r"((uint32_t)(bytes)) : "memory")
#define BULK_COMMIT() asm volatile("cp.async.bulk.commit_group;" ::: "memory")
#define BULK_WAIT0()  asm volatile("cp.async.bulk.wait_group 0;" ::: "memory")
#define FENCE_ASYNC() asm volatile("fence.proxy.async.shared::cta;" ::: "memory")
#define MBAR_WAIT(mb, ph) do {                                                      \
    uint32_t _m = (mb), _p = (uint32_t)(ph), _d;                                    \
    asm volatile("{\n\t.reg .pred p;\n\t"                                           \
        "mbarrier.try_wait.parity.acquire.cta.shared::cta.b64 p, [%1], %2;\n\t"     \
        "selp.b32 %0, 1, 0, p;\n\t}" : "=r"(_d) : "r"(_m), "r"(_p) : "memory");     \
    if (!_d) {                                                                      \
        asm volatile("{\n\t.reg .pred P1;\n\t"                                      \
            "WL_%=:\n\t"                                                            \
            "mbarrier.try_wait.parity.acquire.cta.shared::cta.b64 P1, [%0], %1, 0x989680;\n\t" \
            "@P1 bra.uni WD_%=;\n\tbra.uni WL_%=;\n\tWD_%=:\n\t}"                   \
            :: "r"(_m), "r"(_p) : "memory");                                        \
    } } while (0)

#define MMA_F16(acc, a, bx, by)                                                      \
    asm volatile("mma.sync.aligned.m16n8k16.row.col.f32.f16.f16.f32 "                \
                 "{%0,%1,%2,%3}, {%4,%5,%6,%7}, {%8,%9}, {%0,%1,%2,%3};"             \
                 : "+f"((acc)[0]), "+f"((acc)[1]), "+f"((acc)[2]), "+f"((acc)[3])    \
                 : "r"((a)[0]), "r"((a)[1]), "r"((a)[2]), "r"((a)[3]),               \
                   "r"(bx), "r"(by))

__device__ __forceinline__ uint32_t h2u(__half2 h) { return *reinterpret_cast<uint32_t*>(&h); }

// A-fragment loader from image chunk (words base sw), conflict-free (stride 20)
#define LOAD_A(a, sw, r0, kk2, t, g)                                                 \
    do {                                                                             \
        _Pragma("unroll")                                                            \
        for (int mt = 0; mt < 2; mt++) {                                             \
            const int rb = (r0) + mt * 16 + (g);                                     \
            const int b0 = rb * 20 + (kk2) * 8;                                      \
            const int b1 = (rb + 8) * 20 + (kk2) * 8;                                \
            a[mt][0] = (sw)[b0 + (t)];                                               \
            a[mt][1] = (sw)[b1 + (t)];                                               \
            a[mt][2] = (sw)[b0 + (t) + 4];                                           \
            a[mt][3] = (sw)[b1 + (t) + 4];                                           \
        }                                                                            \
    } while (0)

// ---------------- obs -> fp16 image ----------------
__global__ void conv_img(const float* __restrict__ s, __half* __restrict__ img)
{
    int gid = blockIdx.x * blockDim.x + threadIdx.x;
    if (gid >= MTOT * 16) return;
    const int r = gid >> 4, q = gid & 15;
    float4 v0 = *(const float4*)(s + (size_t)r * 128 + q * 8);
    float4 v1 = *(const float4*)(s + (size_t)r * 128 + q * 8 + 4);
    uint4 o;
    o.x = h2u(__floats2half2_rn(v0.x, v0.y));
    o.y = h2u(__floats2half2_rn(v0.z, v0.w));
    o.z = h2u(__floats2half2_rn(v1.x, v1.y));
    o.w = h2u(__floats2half2_rn(v1.z, v1.w));
    const size_t a = ((size_t)((r >> 7) * 4 + (q >> 2)) * 128 + (r & 127)) * 40 + (q & 3) * 8;
    *(uint4*)(img + a) = o;
}

// ---------------- prep: fold + pack fp16 fragments ----------------
__device__ __forceinline__ float wcomb_elem(int k, int n,
                                            const float* __restrict__ out_w,
                                            const float* __restrict__ int_w1)
{
    if (k < 128) return int_w1[(size_t)k * 256 + n];
    const int c = k - 128;
    float s = 0.f;
#pragma unroll 4
    for (int m = 0; m < 64; m++)
        s = fmaf(out_w[c * 64 + m], int_w1[(size_t)(128 + m) * 256 + n], s);
    return s;
}

__global__ void pack_all(const float* __restrict__ enc_w1, const float* __restrict__ enc_w2,
                         const float* __restrict__ inp_w,  const float* __restrict__ out_w,
                         const float* __restrict__ out_b,  const float* __restrict__ int_w1,
                         const float* __restrict__ int_b1, const float* __restrict__ int_w2)
{
    const int gid = blockIdx.x * blockDim.x + threadIdx.x;
    int p, N = 0;
    const float* W = nullptr;
    uint2* dst = nullptr;
    bool i1 = false;
    if (gid < 4096)        { p = gid;         W = enc_w1; dst = g_packh + PH_E1; N = 128; }
    else if (gid < 6144)   { p = gid - 4096;  W = enc_w2; dst = g_packh + PH_E2; N = 64;  }
    else if (gid < 9216)   { p = gid - 6144;  W = inp_w;  dst = g_packh + PH_QK; N = 192; }
    else if (gid < 17408)  { p = gid - 9216;  W = int_w2; dst = g_packh + PH_I2; N = 128; }
    else if (gid < 29696)  { p = gid - 17408; dst = g_packh + PH_I1; N = 256; i1 = true; }
    else if (gid < 29952) {
        const int n = gid - 29696;
        float s = int_b1[n];
        for (int m = 0; m < 64; m++) s = fmaf(out_b[m], int_w1[(size_t)(128 + m) * 256 + n], s);
        g_bc[n] = s;
        return;
    } else return;

    const int lane = p & 31;
    const int tile = p >> 5;
    const int nt = N >> 3;
    const int j = tile % nt, kk = tile / nt;
    const int t = lane & 3, g = lane >> 2;
    const int k0 = kk * 16, n = j * 8 + g;
    float w0, w1, w2, w3;
    if (i1) {
        w0 = wcomb_elem(k0 + 2 * t,     n, out_w, int_w1);
        w1 = wcomb_elem(k0 + 2 * t + 1, n, out_w, int_w1);
        w2 = wcomb_elem(k0 + 2 * t + 8, n, out_w, int_w1);
        w3 = wcomb_elem(k0 + 2 * t + 9, n, out_w, int_w1);
    } else {
        w0 = W[(size_t)(k0 + 2 * t) * N + n];
        w1 = W[(size_t)(k0 + 2 * t + 1) * N + n];
        w2 = W[(size_t)(k0 + 2 * t + 8) * N + n];
        w3 = W[(size_t)(k0 + 2 * t + 9) * N + n];
    }
    uint2 v;
    v.x = h2u(__floats2half2_rn(w0, w1));
    v.y = h2u(__floats2half2_rn(w2, w3));
    dst[p] = v;
}

// ================= enc1+enc2 fused: obs -> h -> msgs =================
// smem (words): b1 @0(128), b2 @128(64), mbar @192, A1 obs img @256 (10240),
//               A2 h img @10496 (10240), B 2x2048 @20736  | msgs stage reuses @256
#define E_SM_W 24832
__global__ void __launch_bounds__(512)
enc12_kernel(const __half* __restrict__ obs_img,
             const uint2* __restrict__ packE1, const uint2* __restrict__ packE2,
             const float* __restrict__ b1, const float* __restrict__ b2,
             float* __restrict__ msgs32, __half* __restrict__ msgs_img)
{
    extern __shared__ float sm[];
    const int tid = threadIdx.x;
    const int tile = blockIdx.x;
    const uint32_t sbase = smem_u32(sm);
    const uint32_t mb0 = sbase + 192 * 4, mb1 = sbase + 194 * 4;

    if (tid < 128) sm[tid] = b1[tid];
    if (tid < 64)  sm[128 + tid] = b2[tid];
    if (tid == 0) { MBAR_INIT(mb0, 1); MBAR_INIT(mb1, 1); }
    __syncthreads();

    auto bsrc = [&](int cc) -> const char* {
        return (cc < 4) ? (const char*)packE1 + cc * 8192
                        : (const char*)packE2 + (cc - 4) * 4096;
    };
    auto bbytes = [&](int cc) -> uint32_t { return cc < 4 ? 8192u : 4096u; };

    if (tid == 0) {
        MBAR_EXPECT(mb0, 40960 + bbytes(0));
        BULK_G2S(sbase + 256 * 4, obs_img + (size_t)tile * 4 * CH_H, 40960, mb0);
        BULK_G2S(sbase + 20736 * 4, bsrc(0), bbytes(0), mb0);
        MBAR_EXPECT(mb1, bbytes(1));
        BULK_G2S(sbase + (20736 + 2048) * 4, bsrc(1), bbytes(1), mb1);
    }

    const int lane = tid & 31, w = tid >> 5;
    const int wr = w >> 2, wc = w & 3;
    const int t = lane & 3, g = lane >> 2;
    const int r0 = wr * 32;

    // ---- enc1: N=128, NT=4 ----
    float acc1[2][4][4];
#pragma unroll
    for (int mt = 0; mt < 2; mt++)
#pragma unroll
        for (int j = 0; j < 4; j++)
            acc1[mt][j][0] = acc1[mt][j][1] = acc1[mt][j][2] = acc1[mt][j][3] = 0.f;

#pragma unroll 1
    for (int cc = 0; cc < 4; cc++) {
        MBAR_WAIT((cc & 1) ? mb1 : mb0, (cc >> 1) & 1);
        const uint32_t* sw = (const uint32_t*)(sm + 256 + cc * 2560);
        const uint2*    sB = (const uint2*)(sm + 20736 + (cc & 1) * 2048);
#pragma unroll
        for (int kk2 = 0; kk2 < 2; kk2++) {
            uint32_t a[2][4];
            LOAD_A(a, sw, r0, kk2, t, g);
#pragma unroll
            for (int j = 0; j < 4; j++) {
                const uint2 bv = sB[(size_t)(kk2 * 16 + wc * 4 + j) * 32 + lane];
#pragma unroll
                for (int mt = 0; mt < 2; mt++) MMA_F16(acc1[mt][j], a[mt], bv.x, bv.y);
            }
        }
        __syncthreads();
        if (cc + 2 < 8 && tid == 0) {
            const uint32_t mb = (cc & 1) ? mb1 : mb0;
            MBAR_EXPECT(mb, bbytes(cc + 2));
            BULK_G2S(sbase + (20736 + (cc & 1) * 2048) * 4, bsrc(cc + 2), bbytes(cc + 2), mb);
        }
    }
    // epilogue1: relu+bias -> h image in smem (A2)
    {
        __half* hA2 = (__half*)(sm + 10496);
#pragma unroll
        for (int mt = 0; mt < 2; mt++)
#pragma unroll
            for (int j = 0; j < 4; j++) {
                const int n0 = wc * 32 + j * 8 + 2 * t;
                const float b_0 = sm[n0], b_1 = sm[n0 + 1];
                const int rl = r0 + mt * 16 + g;
                const size_t off = (size_t)(n0 >> 5) * CH_H + (n0 & 31);
                *(__half2*)(hA2 + off + (size_t)rl * 40) = __floats2half2_rn(
                    fmaxf(acc1[mt][j][0] + b_0, 0.f), fmaxf(acc1[mt][j][1] + b_1, 0.f));
                *(__half2*)(hA2 + off + (size_t)(rl + 8) * 40) = __floats2half2_rn(
                    fmaxf(acc1[mt][j][2] + b_0, 0.f), fmaxf(acc1[mt][j][3] + b_1, 0.f));
            }
    }
    __syncthreads();

    // ---- enc2: N=64, NT=2 ----
    float acc2[2][2][4];
#pragma unroll
    for (int mt = 0; mt < 2; mt++)
#pragma unroll
        for (int j = 0; j < 2; j++)
            acc2[mt][j][0] = acc2[mt][j][1] = acc2[mt][j][2] = acc2[mt][j][3] = 0.f;

#pragma unroll 1
    for (int c2 = 0; c2 < 4; c2++) {
        const int cc = 4 + c2;
        MBAR_WAIT((cc & 1) ? mb1 : mb0, (cc >> 1) & 1);
        const uint32_t* sw = (const uint32_t*)(sm + 10496 + c2 * 2560);
        const uint2*    sB = (const uint2*)(sm + 20736 + (cc & 1) * 2048);
#pragma unroll
        for (int kk2 = 0; kk2 < 2; kk2++) {
            uint32_t a[2][4];
            LOAD_A(a, sw, r0, kk2, t, g);
#pragma unroll
            for (int j = 0; j < 2; j++) {
                const uint2 bv = sB[(size_t)(kk2 * 8 + wc * 2 + j) * 32 + lane];
#pragma unroll
                for (int mt = 0; mt < 2; mt++) MMA_F16(acc2[mt][j], a[mt], bv.x, bv.y);
            }
        }
        __syncthreads();
        if (cc + 2 < 8 && tid == 0) {
            const uint32_t mb = (cc & 1) ? mb1 : mb0;
            MBAR_EXPECT(mb, bbytes(cc + 2));
            BULK_G2S(sbase + (20736 + (cc & 1) * 2048) * 4, bsrc(cc + 2), bbytes(cc + 2), mb);
        }
    }
    // epilogue2: bias -> msgs fp32 (gmem) + msgs image stage (smem @256)
    {
        __half* stg = (__half*)(sm + 256);
#pragma unroll
        for (int mt = 0; mt < 2; mt++)
#pragma unroll
            for (int j = 0; j < 2; j++) {
                const int n0 = wc * 16 + j * 8 + 2 * t;
                const float b_0 = sm[128 + n0], b_1 = sm[128 + n0 + 1];
                const int rl = r0 + mt * 16 + g;
                const float v0 = acc2[mt][j][0] + b_0, v1 = acc2[mt][j][1] + b_1;
                const float v2 = acc2[mt][j][2] + b_0, v3 = acc2[mt][j][3] + b_1;
                *(float2*)(msgs32 + (size_t)(tile * 128 + rl) * 64 + n0)       = make_float2(v0, v1);
                *(float2*)(msgs32 + (size_t)(tile * 128 + rl + 8) * 64 + n0)   = make_float2(v2, v3);
                const size_t off = (size_t)(n0 >> 5) * CH_H + (n0 & 31);
                *(__half2*)(stg + off + (size_t)rl * 40)       = __floats2half2_rn(v0, v1);
                *(__half2*)(stg + off + (size_t)(rl + 8) * 40) = __floats2half2_rn(v2, v3);
            }
    }
    __syncthreads();
    if (tid == 0) {
        FENCE_ASYNC();
        BULK_S2G(msgs_img + (size_t)tile * 2 * CH_H, sbase + 256 * 4, 20480);
        BULK_COMMIT();
        BULK_WAIT0();
    }
}

// ================= qkv + attention fused =================
// smem (words): inp_b @0(192), mbar @192, A msgs img @256 (5120), B 2x3072 @5376,
//               qkv fp16 stage [128][200] @11520 (12800) | ctx stage reuses @256
#define Q_SM_W 24320
__global__ void __launch_bounds__(512)
qkvattn_kernel(const __half* __restrict__ msgs_img, const uint2* __restrict__ packQK,
               const float* __restrict__ inp_b, __half* __restrict__ ctx_img)
{
    extern __shared__ float sm[];
    const int tid = threadIdx.x;
    const int tile = blockIdx.x;
    const uint32_t sbase = smem_u32(sm);
    const uint32_t mb0 = sbase + 192 * 4, mb1 = sbase + 194 * 4;

    if (tid < 192) sm[tid] = inp_b[tid];
    if (tid == 0) { MBAR_INIT(mb0, 1); MBAR_INIT(mb1, 1); }
    __syncthreads();

    if (tid == 0) {
        MBAR_EXPECT(mb0, 20480 + 12288);
        BULK_G2S(sbase + 256 * 4, msgs_img + (size_t)tile * 2 * CH_H, 20480, mb0);
        BULK_G2S(sbase + 5376 * 4, (const char*)packQK, 12288, mb0);
        MBAR_EXPECT(mb1, 12288);
        BULK_G2S(sbase + (5376 + 3072) * 4, (const char*)packQK + 12288, 12288, mb1);
    }

    const int lane = tid & 31, w = tid >> 5;
    const int wr = w >> 2, wc = w & 3;
    const int t = lane & 3, g = lane >> 2;
    const int r0 = wr * 32;

    float acc[2][6][4];
#pragma unroll
    for (int mt = 0; mt < 2; mt++)
#pragma unroll
        for (int j = 0; j < 6; j++)
            acc[mt][j][0] = acc[mt][j][1] = acc[mt][j][2] = acc[mt][j][3] = 0.f;

#pragma unroll 1
    for (int cc = 0; cc < 2; cc++) {
        MBAR_WAIT(cc ? mb1 : mb0, 0);
        const uint32_t* sw = (const uint32_t*)(sm + 256 + cc * 2560);
        const uint2*    sB = (const uint2*)(sm + 5376 + cc * 3072);
#pragma unroll
        for (int kk2 = 0; kk2 < 2; kk2++) {
            uint32_t a[2][4];
            LOAD_A(a, sw, r0, kk2, t, g);
#pragma unroll
            for (int j = 0; j < 6; j++) {
                const uint2 bv = sB[(size_t)(kk2 * 24 + wc * 6 + j) * 32 + lane];
#pragma unroll
                for (int mt = 0; mt < 2; mt++) MMA_F16(acc[mt][j], a[mt], bv.x, bv.y);
            }
        }
        __syncthreads();
    }
    // epilogue: bias -> qkv fp16 stage [row][200]
    {
        __half* stg = (__half*)(sm + 11520);
#pragma unroll
        for (int mt = 0; mt < 2; mt++)
#pragma unroll
            for (int j = 0; j < 6; j++) {
                const int n0 = wc * 48 + j * 8 + 2 * t;
                const float b_0 = sm[n0], b_1 = sm[n0 + 1];
                const int rl = r0 + mt * 16 + g;
                *(__half2*)(stg + (size_t)rl * 200 + n0) = __floats2half2_rn(
                    acc[mt][j][0] + b_0, acc[mt][j][1] + b_1);
                *(__half2*)(stg + (size_t)(rl + 8) * 200 + n0) = __floats2half2_rn(
                    acc[mt][j][2] + b_0, acc[mt][j][3] + b_1);
            }
    }
    __syncthreads();

    // attention: 512 thr = 2 batches x 4 heads x 64 queries
    {
        const __half* sQ = (const __half*)(sm + 11520);
        const int lb = tid >> 8, hh = (tid >> 6) & 3, q = tid & 63;
        const int qrow = lb * 64 + q;
        float qv[16];
        {
            const __half2* p = (const __half2*)(sQ + (size_t)qrow * 200 + hh * 16);
#pragma unroll
            for (int d = 0; d < 8; d++) {
                float2 f = __half22float2(p[d]);
                qv[2 * d] = f.x; qv[2 * d + 1] = f.y;
            }
        }
        float m = -1e30f;
#pragma unroll 4
        for (int k = 0; k < 64; k++) {
            const __half2* kp = (const __half2*)(sQ + (size_t)(lb * 64 + k) * 200 + 64 + hh * 16);
            float s = 0.f;
#pragma unroll
            for (int d = 0; d < 8; d++) {
                float2 f = __half22float2(kp[d]);
                s = fmaf(qv[2 * d], f.x, s);
                s = fmaf(qv[2 * d + 1], f.y, s);
            }
            m = fmaxf(m, s * 0.25f);
        }
        float ssum = 0.f, cx[16];
#pragma unroll
        for (int d = 0; d < 16; d++) cx[d] = 0.f;
#pragma unroll 2
        for (int k = 0; k < 64; k++) {
            const __half* rowp = sQ + (size_t)(lb * 64 + k) * 200;
            const __half2* kp = (const __half2*)(rowp + 64 + hh * 16);
            float s = 0.f;
#pragma unroll
            for (int d = 0; d < 8; d++) {
                float2 f = __half22float2(kp[d]);
                s = fmaf(qv[2 * d], f.x, s);
                s = fmaf(qv[2 * d + 1], f.y, s);
            }
            const float p = __expf(fmaf(s, 0.25f, -m));
            ssum += p;
            const __half2* vp = (const __half2*)(rowp + 128 + hh * 16);
#pragma unroll
            for (int d = 0; d < 8; d++) {
                float2 f = __half22float2(vp[d]);
                cx[2 * d] = fmaf(p, f.x, cx[2 * d]);
                cx[2 * d + 1] = fmaf(p, f.y, cx[2 * d + 1]);
            }
        }
        const float inv = 1.f / ssum;
        __half* stg = (__half*)(sm + 256);   // ctx image stage (A region dead)
#pragma unroll
        for (int d = 0; d < 8; d++) {
            const int c = hh * 16 + 2 * d;
            *(__half2*)(stg + (size_t)(c >> 5) * CH_H + (size_t)qrow * 40 + (c & 31)) =
                __floats2half2_rn(cx[2 * d] * inv, cx[2 * d + 1] * inv);
        }
    }
    __syncthreads();
    if (tid == 0) {
        FENCE_ASYNC();
        BULK_S2G(ctx_img + (size_t)tile * 2 * CH_H, sbase + 256 * 4, 20480);
        BULK_COMMIT();
        BULK_WAIT0();
    }
}

// ================= int1: [obs|ctx] -> LN(relu(...)) -> z image =================
// smem (words): bc @0(256), lng @256, lnb @512, reduce @768(1024), mbar @1792,
//               A @1808 (6x2560=15360), B 2x4096 @17168 | z stage reuses @1808 (20480)
#define I1_SM_W 25360
__global__ void __launch_bounds__(512)
int1_kernel(const __half* __restrict__ obs_img, const __half* __restrict__ ctx_img,
            const uint2* __restrict__ packI1, const float* __restrict__ bc,
            const float* __restrict__ lng, const float* __restrict__ lnb,
            __half* __restrict__ z_img)
{
    extern __shared__ float sm[];
    const int tid = threadIdx.x;
    const int tile = blockIdx.x;
    const uint32_t sbase = smem_u32(sm);
    const uint32_t mb0 = sbase + 1792 * 4, mb1 = sbase + 1794 * 4;

    if (tid < 256) { sm[tid] = bc[tid]; sm[256 + tid] = lng[tid]; sm[512 + tid] = lnb[tid]; }
    if (tid == 0) { MBAR_INIT(mb0, 1); MBAR_INIT(mb1, 1); }
    __syncthreads();

    if (tid == 0) {
        MBAR_EXPECT(mb0, 40960 + 20480 + 16384);
        BULK_G2S(sbase + 1808 * 4, obs_img + (size_t)tile * 4 * CH_H, 40960, mb0);
        BULK_G2S(sbase + (1808 + 4 * 2560) * 4, ctx_img + (size_t)tile * 2 * CH_H, 20480, mb0);
        BULK_G2S(sbase + 17168 * 4, (const char*)packI1, 16384, mb0);
        MBAR_EXPECT(mb1, 16384);
        BULK_G2S(sbase + (17168 + 4096) * 4, (const char*)packI1 + 16384, 16384, mb1);
    }

    const int lane = tid & 31, w = tid >> 5;
    const int wr = w >> 2, wc = w & 3;
    const int t = lane & 3, g = lane >> 2;
    const int r0 = wr * 32;

    float acc[2][8][4];
#pragma unroll
    for (int mt = 0; mt < 2; mt++)
#pragma unroll
        for (int j = 0; j < 8; j++)
            acc[mt][j][0] = acc[mt][j][1] = acc[mt][j][2] = acc[mt][j][3] = 0.f;

#pragma unroll 1
    for (int cc = 0; cc < 6; cc++) {
        MBAR_WAIT((cc & 1) ? mb1 : mb0, (cc >> 1) & 1);
        const uint32_t* sw = (const uint32_t*)(sm + 1808 + cc * 2560);
        const uint2*    sB = (const uint2*)(sm + 17168 + (cc & 1) * 4096);
#pragma unroll
        for (int kk2 = 0; kk2 < 2; kk2++) {
            uint32_t a[2][4];
            LOAD_A(a, sw, r0, kk2, t, g);
#pragma unroll
            for (int j = 0; j < 8; j++) {
                const uint2 bv = sB[(size_t)(kk2 * 32 + wc * 8 + j) * 32 + lane];
#pragma unroll
                for (int mt = 0; mt < 2; mt++) MMA_F16(acc[mt][j], a[mt], bv.x, bv.y);
            }
        }
        __syncthreads();
        if (cc + 2 < 6 && tid == 0) {
            const uint32_t mb = (cc & 1) ? mb1 : mb0;
            MBAR_EXPECT(mb, 16384);
            BULK_G2S(sbase + (17168 + (cc & 1) * 4096) * 4,
                     (const char*)packI1 + (size_t)(cc + 2) * 16384, 16384, mb);
        }
    }

    // epilogue: bias + LayerNorm + relu -> z image stage
#pragma unroll
    for (int mt = 0; mt < 2; mt++)
#pragma unroll
        for (int j = 0; j < 8; j++) {
            const int n0 = wc * 64 + j * 8 + 2 * t;
            acc[mt][j][0] += sm[n0]; acc[mt][j][1] += sm[n0 + 1];
            acc[mt][j][2] += sm[n0]; acc[mt][j][3] += sm[n0 + 1];
        }
    float ps[2][2] = {{0,0},{0,0}}, pq[2][2] = {{0,0},{0,0}};
#pragma unroll
    for (int mt = 0; mt < 2; mt++)
#pragma unroll
        for (int j = 0; j < 8; j++) {
            ps[mt][0] += acc[mt][j][0] + acc[mt][j][1];
            pq[mt][0] += acc[mt][j][0] * acc[mt][j][0] + acc[mt][j][1] * acc[mt][j][1];
            ps[mt][1] += acc[mt][j][2] + acc[mt][j][3];
            pq[mt][1] += acc[mt][j][2] * acc[mt][j][2] + acc[mt][j][3] * acc[mt][j][3];
        }
#pragma unroll
    for (int mt = 0; mt < 2; mt++)
#pragma unroll
        for (int h = 0; h < 2; h++) {
            ps[mt][h] += __shfl_xor_sync(0xffffffffu, ps[mt][h], 1);
            ps[mt][h] += __shfl_xor_sync(0xffffffffu, ps[mt][h], 2);
            pq[mt][h] += __shfl_xor_sync(0xffffffffu, pq[mt][h], 1);
            pq[mt][h] += __shfl_xor_sync(0xffffffffu, pq[mt][h], 2);
        }
    if (t == 0) {
#pragma unroll
        for (int mt = 0; mt < 2; mt++)
#pragma unroll
            for (int h = 0; h < 2; h++) {
                const int rl = r0 + mt * 16 + g + 8 * h;
                sm[768 + rl * 4 + wc]       = ps[mt][h];
                sm[768 + 512 + rl * 4 + wc] = pq[mt][h];
            }
    }
    __syncthreads();
    float mu[2][2], rs[2][2];
#pragma unroll
    for (int mt = 0; mt < 2; mt++)
#pragma unroll
        for (int h = 0; h < 2; h++) {
            const int rl = r0 + mt * 16 + g + 8 * h;
            const float s_ = sm[768 + rl * 4] + sm[768 + rl * 4 + 1]
                           + sm[768 + rl * 4 + 2] + sm[768 + rl * 4 + 3];
            const float q_ = sm[1280 + rl * 4] + sm[1280 + rl * 4 + 1]
                           + sm[1280 + rl * 4 + 2] + sm[1280 + rl * 4 + 3];
            const float m_ = s_ * (1.f / 256.f);
            const float v_ = q_ * (1.f / 256.f) - m_ * m_;
            mu[mt][h] = m_;
            rs[mt][h] = rsqrtf(v_ + 1e-5f);
        }
    {
        __half* stg = (__half*)(sm + 1808);
#pragma unroll
        for (int mt = 0; mt < 2; mt++)
#pragma unroll
            for (int j = 0; j < 8; j++) {
                const int n0 = wc * 64 + j * 8 + 2 * t;
                const float g0 = sm[256 + n0], g1 = sm[256 + n0 + 1];
                const float b0 = sm[512 + n0], b1 = sm[512 + n0 + 1];
                const int rl = r0 + mt * 16 + g;
                const size_t off = (size_t)(n0 >> 5) * CH_H + (n0 & 31);
                *(__half2*)(stg + off + (size_t)rl * 40) = __floats2half2_rn(
                    fmaxf((acc[mt][j][0] - mu[mt][0]) * rs[mt][0] * g0 + b0, 0.f),
                    fmaxf((acc[mt][j][1] - mu[mt][0]) * rs[mt][0] * g1 + b1, 0.f));
                *(__half2*)(stg + off + (size_t)(rl + 8) * 40) = __floats2half2_rn(
                    fmaxf((acc[mt][j][2] - mu[mt][1]) * rs[mt][1] * g0 + b0, 0.f),
                    fmaxf((acc[mt][j][3] - mu[mt][1]) * rs[mt][1] * g1 + b1, 0.f));
            }
    }
    __syncthreads();
    if (tid == 0) {
        FENCE_ASYNC();
        BULK_S2G(z_img + (size_t)tile * 8 * CH_H, sbase + 1808 * 4, 81920);
        BULK_COMMIT();
        BULK_WAIT0();
    }
}

// ================= int2: z -> enriched (fp32 out) =================
// smem (words): b2 @0(128), mbar @192, A z img @256 (20480), B 2x2048 @20736
#define I2_SM_W 24832
__global__ void __launch_bounds__(512)
int2_kernel(const __half* __restrict__ z_img, const uint2* __restrict__ packI2,
            const float* __restrict__ ib2, float* __restrict__ outE)
{
    extern __shared__ float sm[];
    const int tid = threadIdx.x;
    const int tile = blockIdx.x;
    const uint32_t sbase = smem_u32(sm);
    const uint32_t mb0 = sbase + 192 * 4, mb1 = sbase + 194 * 4;

    if (tid < 128) sm[tid] = ib2[tid];
    if (tid == 0) { MBAR_INIT(mb0, 1); MBAR_INIT(mb1, 1); }
    __syncthreads();

    if (tid == 0) {
        MBAR_EXPECT(mb0, 81920 + 8192);
        BULK_G2S(sbase + 256 * 4, z_img + (size_t)tile * 8 * CH_H, 81920, mb0);
        BULK_G2S(sbase + 20736 * 4, (const char*)packI2, 8192, mb0);
        MBAR_EXPECT(mb1, 8192);
        BULK_G2S(sbase + (20736 + 2048) * 4, (const char*)packI2 + 8192, 8192, mb1);
    }

    const int lane = tid & 31, w = tid >> 5;
    const int wr = w >> 2, wc = w & 3;
    const int t = lane & 3, g = lane >> 2;
    const int r0 = wr * 32;

    float acc[2][4][4];
#pragma unroll
    for (int mt = 0; mt < 2; mt++)
#pragma unroll
        for (int j = 0; j < 4; j++)
            acc[mt][j][0] = acc[mt][j][1] = acc[mt][j][2] = acc[mt][j][3] = 0.f;

#pragma unroll 1
    for (int cc = 0; cc < 8; cc++) {
        MBAR_WAIT((cc & 1) ? mb1 : mb0, (cc >> 1) & 1);
        const uint32_t* sw = (const uint32_t*)(sm + 256 + cc * 2560);
        const uint2*    sB = (const uint2*)(sm + 20736 + (cc & 1) * 2048);
#pragma unroll
        for (int kk2 = 0; kk2 < 2; kk2++) {
            uint32_t a[2][4];
            LOAD_A(a, sw, r0, kk2, t, g);
#pragma unroll
            for (int j = 0; j < 4; j++) {
                const uint2 bv = sB[(size_t)(kk2 * 16 + wc * 4 + j) * 32 + lane];
#pragma unroll
                for (int mt = 0; mt < 2; mt++) MMA_F16(acc[mt][j], a[mt], bv.x, bv.y);
            }
        }
        __syncthreads();
        if (cc + 2 < 8 && tid == 0) {
            const uint32_t mb = (cc & 1) ? mb1 : mb0;
            MBAR_EXPECT(mb, 8192);
            BULK_G2S(sbase + (20736 + (cc & 1) * 2048) * 4,
                     (const char*)packI2 + (size_t)(cc + 2) * 8192, 8192, mb);
        }
    }
#pragma unroll
    for (int mt = 0; mt < 2; mt++)
#pragma unroll
        for (int j = 0; j < 4; j++) {
            const int n0 = wc * 32 + j * 8 + 2 * t;
            const float b_0 = sm[n0], b_1 = sm[n0 + 1];
            const int rl = r0 + mt * 16 + g;
            *(float2*)(outE + (size_t)(tile * 128 + rl) * 128 + n0) =
                make_float2(acc[mt][j][0] + b_0, acc[mt][j][1] + b_1);
            *(float2*)(outE + (size_t)(tile * 128 + rl + 8) * 128 + n0) =
                make_float2(acc[mt][j][2] + b_0, acc[mt][j][3] + b_1);
        }
}

// ---------------- launch ----------------
extern "C" void kernel_launch(void* const* d_in, const int* in_sizes, int n_in,
                              void* d_out, int out_size)
{
    const float* obs    = (const float*)d_in[0];
    const float* enc_w1 = (const float*)d_in[1];
    const float* enc_b1 = (const float*)d_in[2];
    const float* enc_w2 = (const float*)d_in[3];
    const float* enc_b2 = (const float*)d_in[4];
    const float* inp_w  = (const float*)d_in[5];
    const float* inp_b  = (const float*)d_in[6];
    const float* out_w  = (const float*)d_in[7];
    const float* out_b  = (const float*)d_in[8];
    const float* int_w1 = (const float*)d_in[9];
    const float* int_b1 = (const float*)d_in[10];
    const float* ln_g   = (const float*)d_in[11];
    const float* ln_b   = (const float*)d_in[12];
    const float* int_w2 = (const float*)d_in[13];
    const float* int_b2 = (const float*)d_in[14];

    float* outE = (float*)d_out;
    const size_t esz = (size_t)MTOT * DOBS;
    float* outM = ((size_t)out_size > esz) ? outE + esz : nullptr;

    uint2* p_pack;
    float *p_bc, *p_msgs;
    __half *p_obs_i, *p_msgs_i, *p_ctx_i, *p_z_i;
    cudaGetSymbolAddress((void**)&p_pack,   g_packh);
    cudaGetSymbolAddress((void**)&p_bc,     g_bc);
    cudaGetSymbolAddress((void**)&p_obs_i,  g_obs_img);
    cudaGetSymbolAddress((void**)&p_msgs_i, g_msgs_img);
    cudaGetSymbolAddress((void**)&p_ctx_i,  g_ctx_img);
    cudaGetSymbolAddress((void**)&p_z_i,    g_z_img);
    cudaGetSymbolAddress((void**)&p_msgs,   g_msgs_s);
    float* msgs = outM ? outM : p_msgs;

    cudaFuncSetAttribute(enc12_kernel,   cudaFuncAttributeMaxDynamicSharedMemorySize, E_SM_W * 4);
    cudaFuncSetAttribute(qkvattn_kernel, cudaFuncAttributeMaxDynamicSharedMemorySize, Q_SM_W * 4);
    cudaFuncSetAttribute(int1_kernel,    cudaFuncAttributeMaxDynamicSharedMemorySize, I1_SM_W * 4);
    cudaFuncSetAttribute(int2_kernel,    cudaFuncAttributeMaxDynamicSharedMemorySize, I2_SM_W * 4);

    pack_all<<<(29952 + 255) / 256, 256>>>(enc_w1, enc_w2, inp_w, out_w, out_b,
                                           int_w1, int_b1, int_w2);
    conv_img<<<(MTOT * 16 + 511) / 512, 512>>>(obs, p_obs_i);

    enc12_kernel<<<NTILE, 512, E_SM_W * 4>>>(p_obs_i, p_pack + PH_E1, p_pack + PH_E2,
                                             enc_b1, enc_b2, msgs, p_msgs_i);
    qkvattn_kernel<<<NTILE, 512, Q_SM_W * 4>>>(p_msgs_i, p_pack + PH_QK, inp_b, p_ctx_i);
    int1_kernel<<<NTILE, 512, I1_SM_W * 4>>>(p_obs_i, p_ctx_i, p_pack + PH_I1,
                                             p_bc, ln_g, ln_b, p_z_i);
    int2_kernel<<<NTILE, 512, I2_SM_W * 4>>>(p_z_i, p_pack + PH_I2, int_b2, outE);
}

// round 11
// speedup vs baseline: 1.2212x; 1.0812x over previous
#include <cuda_runtime.h>
#include <cuda_fp16.h>
#include <math.h>
#include <stdint.h>

// ---------------- problem constants ----------------
#define NBATCH 4096
#define NTOK   64
#define MTOT   (NBATCH * NTOK)
#define DOBS   128
#define NTILE  (MTOT / 128)        // 2048
#define CH_H   5120                // halves per image chunk (128 rows x 40)

// ---------------- packed fp16 weight fragments ----------------
#define PH_E1  0
#define PH_E2  4096
#define PH_QK  6144
#define PH_I2  9216
#define PH_I1  17408
#define PH_TOT 29696
__device__ uint2  g_packh[PH_TOT];
__device__ float  g_bc[256];
__device__ __half g_obs_img[(size_t)NTILE * 4 * CH_H];
__device__ __half g_msgs_img[(size_t)NTILE * 2 * CH_H];
__device__ __half g_ctx_img[(size_t)NTILE * 2 * CH_H];
__device__ __half g_z_img[(size_t)NTILE * 8 * CH_H];
__device__ float  g_msgs_s[(size_t)MTOT * 64];

// ---------------- helpers ----------------
__device__ __forceinline__ uint32_t smem_u32(const void* p) {
    uint32_t a;
    asm("{ .reg .u64 t; cvta.to.shared.u64 t, %1; cvt.u32.u64 %0, t; }" : "=r"(a) : "l"(p));
    return a;
}
#define MBAR_INIT(mb, c) \
    asm volatile("mbarrier.init.shared.b64 [%0], %1;" :: "r"(mb), "r"((uint32_t)(c)) : "memory")
#define MBAR_EXPECT(mb, tx) \
    asm volatile("mbarrier.arrive.expect_tx.shared.b64 _, [%0], %1;" :: "r"(mb), "r"((uint32_t)(tx)) : "memory")
#define BULK_G2S(dst, src, bytes, mb) \
    asm volatile("cp.async.bulk.shared::cta.global.mbarrier::complete_tx::bytes [%0], [%1], %2, [%3];" \
                 :: "r"(dst), "l"(src), "r"((uint32_t)(bytes)), "r"(mb) : "memory")
#define BULK_S2G(gdst, ssrc, bytes) \
    asm volatile("cp.async.bulk.global.shared::cta.bulk_group [%0], [%1], %2;" \
                 :: "l"(gdst), "r"(ssrc), "r"((uint32_t)(bytes)) : "memory")
#define BULK_COMMIT() asm volatile("cp.async.bulk.commit_group;" ::: "memory")
#define BULK_WAIT0()  asm volatile("cp.async.bulk.wait_group 0;" ::: "memory")
#define FENCE_ASYNC() asm volatile("fence.proxy.async.shared::cta;" ::: "memory")
#define MBAR_WAIT(mb, ph) do {                                                      \
    uint32_t _m = (mb), _p = (uint32_t)(ph), _d;                                    \
    asm volatile("{\n\t.reg .pred p;\n\t"                                           \
        "mbarrier.try_wait.parity.acquire.cta.shared::cta.b64 p, [%1], %2;\n\t"     \
        "selp.b32 %0, 1, 0, p;\n\t}" : "=r"(_d) : "r"(_m), "r"(_p) : "memory");     \
    if (!_d) {                                                                      \
        asm volatile("{\n\t.reg .pred P1;\n\t"                                      \
            "WL_%=:\n\t"                                                            \
            "mbarrier.try_wait.parity.acquire.cta.shared::cta.b64 P1, [%0], %1, 0x989680;\n\t" \
            "@P1 bra.uni WD_%=;\n\tbra.uni WL_%=;\n\tWD_%=:\n\t}"                   \
            :: "r"(_m), "r"(_p) : "memory");                                        \
    } } while (0)

#define MMA_F16(acc, a, bx, by)                                                      \
    asm volatile("mma.sync.aligned.m16n8k16.row.col.f32.f16.f16.f32 "                \
                 "{%0,%1,%2,%3}, {%4,%5,%6,%7}, {%8,%9}, {%0,%1,%2,%3};"             \
                 : "+f"((acc)[0]), "+f"((acc)[1]), "+f"((acc)[2]), "+f"((acc)[3])    \
                 : "r"((a)[0]), "r"((a)[1]), "r"((a)[2]), "r"((a)[3]),               \
                   "r"(bx), "r"(by))

__device__ __forceinline__ uint32_t h2u(__half2 h) { return *reinterpret_cast<uint32_t*>(&h); }
__device__ __forceinline__ float ex2f(float x) {
    float r;
    asm("ex2.approx.f32 %0, %1;" : "=f"(r) : "f"(x));
    return r;
}

// A-fragment loader from image chunk (words base sw), conflict-free (stride 20)
#define LOAD_A(a, sw, r0, kk2, t, g)                                                 \
    do {                                                                             \
        _Pragma("unroll")                                                            \
        for (int mt = 0; mt < 2; mt++) {                                             \
            const int rb = (r0) + mt * 16 + (g);                                     \
            const int b0 = rb * 20 + (kk2) * 8;                                      \
            const int b1 = (rb + 8) * 20 + (kk2) * 8;                                \
            a[mt][0] = (sw)[b0 + (t)];                                               \
            a[mt][1] = (sw)[b1 + (t)];                                               \
            a[mt][2] = (sw)[b0 + (t) + 4];                                           \
            a[mt][3] = (sw)[b1 + (t) + 4];                                           \
        }                                                                            \
    } while (0)

// ---------------- obs -> fp16 image ----------------
__global__ void conv_img(const float* __restrict__ s, __half* __restrict__ img)
{
    int gid = blockIdx.x * blockDim.x + threadIdx.x;
    if (gid >= MTOT * 16) return;
    const int r = gid >> 4, q = gid & 15;
    float4 v0 = *(const float4*)(s + (size_t)r * 128 + q * 8);
    float4 v1 = *(const float4*)(s + (size_t)r * 128 + q * 8 + 4);
    uint4 o;
    o.x = h2u(__floats2half2_rn(v0.x, v0.y));
    o.y = h2u(__floats2half2_rn(v0.z, v0.w));
    o.z = h2u(__floats2half2_rn(v1.x, v1.y));
    o.w = h2u(__floats2half2_rn(v1.z, v1.w));
    const size_t a = ((size_t)((r >> 7) * 4 + (q >> 2)) * 128 + (r & 127)) * 40 + (q & 3) * 8;
    *(uint4*)(img + a) = o;
}

// ---------------- prep: fold + pack fp16 fragments ----------------
__device__ __forceinline__ float wcomb_elem(int k, int n,
                                            const float* __restrict__ out_w,
                                            const float* __restrict__ int_w1)
{
    if (k < 128) return int_w1[(size_t)k * 256 + n];
    const int c = k - 128;
    float s = 0.f;
#pragma unroll 4
    for (int m = 0; m < 64; m++)
        s = fmaf(out_w[c * 64 + m], int_w1[(size_t)(128 + m) * 256 + n], s);
    return s;
}

__global__ void pack_all(const float* __restrict__ enc_w1, const float* __restrict__ enc_w2,
                         const float* __restrict__ inp_w,  const float* __restrict__ out_w,
                         const float* __restrict__ out_b,  const float* __restrict__ int_w1,
                         const float* __restrict__ int_b1, const float* __restrict__ int_w2)
{
    const int gid = blockIdx.x * blockDim.x + threadIdx.x;
    int p, N = 0;
    const float* W = nullptr;
    uint2* dst = nullptr;
    bool i1 = false;
    if (gid < 4096)        { p = gid;         W = enc_w1; dst = g_packh + PH_E1; N = 128; }
    else if (gid < 6144)   { p = gid - 4096;  W = enc_w2; dst = g_packh + PH_E2; N = 64;  }
    else if (gid < 9216)   { p = gid - 6144;  W = inp_w;  dst = g_packh + PH_QK; N = 192; }
    else if (gid < 17408)  { p = gid - 9216;  W = int_w2; dst = g_packh + PH_I2; N = 128; }
    else if (gid < 29696)  { p = gid - 17408; dst = g_packh + PH_I1; N = 256; i1 = true; }
    else if (gid < 29952) {
        const int n = gid - 29696;
        float s = int_b1[n];
        for (int m = 0; m < 64; m++) s = fmaf(out_b[m], int_w1[(size_t)(128 + m) * 256 + n], s);
        g_bc[n] = s;
        return;
    } else return;

    const int lane = p & 31;
    const int tile = p >> 5;
    const int nt = N >> 3;
    const int j = tile % nt, kk = tile / nt;
    const int t = lane & 3, g = lane >> 2;
    const int k0 = kk * 16, n = j * 8 + g;
    float w0, w1, w2, w3;
    if (i1) {
        w0 = wcomb_elem(k0 + 2 * t,     n, out_w, int_w1);
        w1 = wcomb_elem(k0 + 2 * t + 1, n, out_w, int_w1);
        w2 = wcomb_elem(k0 + 2 * t + 8, n, out_w, int_w1);
        w3 = wcomb_elem(k0 + 2 * t + 9, n, out_w, int_w1);
    } else {
        w0 = W[(size_t)(k0 + 2 * t) * N + n];
        w1 = W[(size_t)(k0 + 2 * t + 1) * N + n];
        w2 = W[(size_t)(k0 + 2 * t + 8) * N + n];
        w3 = W[(size_t)(k0 + 2 * t + 9) * N + n];
    }
    uint2 v;
    v.x = h2u(__floats2half2_rn(w0, w1));
    v.y = h2u(__floats2half2_rn(w2, w3));
    dst[p] = v;
}

// ================= enc1+enc2 fused (unchanged, validated) =================
#define E_SM_W 24832
__global__ void __launch_bounds__(512)
enc12_kernel(const __half* __restrict__ obs_img,
             const uint2* __restrict__ packE1, const uint2* __restrict__ packE2,
             const float* __restrict__ b1, const float* __restrict__ b2,
             float* __restrict__ msgs32, __half* __restrict__ msgs_img)
{
    extern __shared__ float sm[];
    const int tid = threadIdx.x;
    const int tile = blockIdx.x;
    const uint32_t sbase = smem_u32(sm);
    const uint32_t mb0 = sbase + 192 * 4, mb1 = sbase + 194 * 4;

    if (tid < 128) sm[tid] = b1[tid];
    if (tid < 64)  sm[128 + tid] = b2[tid];
    if (tid == 0) { MBAR_INIT(mb0, 1); MBAR_INIT(mb1, 1); }
    __syncthreads();

    auto bsrc = [&](int cc) -> const char* {
        return (cc < 4) ? (const char*)packE1 + cc * 8192
                        : (const char*)packE2 + (cc - 4) * 4096;
    };
    auto bbytes = [&](int cc) -> uint32_t { return cc < 4 ? 8192u : 4096u; };

    if (tid == 0) {
        MBAR_EXPECT(mb0, 40960 + bbytes(0));
        BULK_G2S(sbase + 256 * 4, obs_img + (size_t)tile * 4 * CH_H, 40960, mb0);
        BULK_G2S(sbase + 20736 * 4, bsrc(0), bbytes(0), mb0);
        MBAR_EXPECT(mb1, bbytes(1));
        BULK_G2S(sbase + (20736 + 2048) * 4, bsrc(1), bbytes(1), mb1);
    }

    const int lane = tid & 31, w = tid >> 5;
    const int wr = w >> 2, wc = w & 3;
    const int t = lane & 3, g = lane >> 2;
    const int r0 = wr * 32;

    float acc1[2][4][4];
#pragma unroll
    for (int mt = 0; mt < 2; mt++)
#pragma unroll
        for (int j = 0; j < 4; j++)
            acc1[mt][j][0] = acc1[mt][j][1] = acc1[mt][j][2] = acc1[mt][j][3] = 0.f;

#pragma unroll 1
    for (int cc = 0; cc < 4; cc++) {
        MBAR_WAIT((cc & 1) ? mb1 : mb0, (cc >> 1) & 1);
        const uint32_t* sw = (const uint32_t*)(sm + 256 + cc * 2560);
        const uint2*    sB = (const uint2*)(sm + 20736 + (cc & 1) * 2048);
#pragma unroll
        for (int kk2 = 0; kk2 < 2; kk2++) {
            uint32_t a[2][4];
            LOAD_A(a, sw, r0, kk2, t, g);
#pragma unroll
            for (int j = 0; j < 4; j++) {
                const uint2 bv = sB[(size_t)(kk2 * 16 + wc * 4 + j) * 32 + lane];
#pragma unroll
                for (int mt = 0; mt < 2; mt++) MMA_F16(acc1[mt][j], a[mt], bv.x, bv.y);
            }
        }
        __syncthreads();
        if (cc + 2 < 8 && tid == 0) {
            const uint32_t mb = (cc & 1) ? mb1 : mb0;
            MBAR_EXPECT(mb, bbytes(cc + 2));
            BULK_G2S(sbase + (20736 + (cc & 1) * 2048) * 4, bsrc(cc + 2), bbytes(cc + 2), mb);
        }
    }
    {
        __half* hA2 = (__half*)(sm + 10496);
#pragma unroll
        for (int mt = 0; mt < 2; mt++)
#pragma unroll
            for (int j = 0; j < 4; j++) {
                const int n0 = wc * 32 + j * 8 + 2 * t;
                const float b_0 = sm[n0], b_1 = sm[n0 + 1];
                const int rl = r0 + mt * 16 + g;
                const size_t off = (size_t)(n0 >> 5) * CH_H + (n0 & 31);
                *(__half2*)(hA2 + off + (size_t)rl * 40) = __floats2half2_rn(
                    fmaxf(acc1[mt][j][0] + b_0, 0.f), fmaxf(acc1[mt][j][1] + b_1, 0.f));
                *(__half2*)(hA2 + off + (size_t)(rl + 8) * 40) = __floats2half2_rn(
                    fmaxf(acc1[mt][j][2] + b_0, 0.f), fmaxf(acc1[mt][j][3] + b_1, 0.f));
            }
    }
    __syncthreads();

    float acc2[2][2][4];
#pragma unroll
    for (int mt = 0; mt < 2; mt++)
#pragma unroll
        for (int j = 0; j < 2; j++)
            acc2[mt][j][0] = acc2[mt][j][1] = acc2[mt][j][2] = acc2[mt][j][3] = 0.f;

#pragma unroll 1
    for (int c2 = 0; c2 < 4; c2++) {
        const int cc = 4 + c2;
        MBAR_WAIT((cc & 1) ? mb1 : mb0, (cc >> 1) & 1);
        const uint32_t* sw = (const uint32_t*)(sm + 10496 + c2 * 2560);
        const uint2*    sB = (const uint2*)(sm + 20736 + (cc & 1) * 2048);
#pragma unroll
        for (int kk2 = 0; kk2 < 2; kk2++) {
            uint32_t a[2][4];
            LOAD_A(a, sw, r0, kk2, t, g);
#pragma unroll
            for (int j = 0; j < 2; j++) {
                const uint2 bv = sB[(size_t)(kk2 * 8 + wc * 2 + j) * 32 + lane];
#pragma unroll
                for (int mt = 0; mt < 2; mt++) MMA_F16(acc2[mt][j], a[mt], bv.x, bv.y);
            }
        }
        __syncthreads();
        if (cc + 2 < 8 && tid == 0) {
            const uint32_t mb = (cc & 1) ? mb1 : mb0;
            MBAR_EXPECT(mb, bbytes(cc + 2));
            BULK_G2S(sbase + (20736 + (cc & 1) * 2048) * 4, bsrc(cc + 2), bbytes(cc + 2), mb);
        }
    }
    {
        __half* stg = (__half*)(sm + 256);
#pragma unroll
        for (int mt = 0; mt < 2; mt++)
#pragma unroll
            for (int j = 0; j < 2; j++) {
                const int n0 = wc * 16 + j * 8 + 2 * t;
                const float b_0 = sm[128 + n0], b_1 = sm[128 + n0 + 1];
                const int rl = r0 + mt * 16 + g;
                const float v0 = acc2[mt][j][0] + b_0, v1 = acc2[mt][j][1] + b_1;
                const float v2 = acc2[mt][j][2] + b_0, v3 = acc2[mt][j][3] + b_1;
                *(float2*)(msgs32 + (size_t)(tile * 128 + rl) * 64 + n0)       = make_float2(v0, v1);
                *(float2*)(msgs32 + (size_t)(tile * 128 + rl + 8) * 64 + n0)   = make_float2(v2, v3);
                const size_t off = (size_t)(n0 >> 5) * CH_H + (n0 & 31);
                *(__half2*)(stg + off + (size_t)rl * 40)       = __floats2half2_rn(v0, v1);
                *(__half2*)(stg + off + (size_t)(rl + 8) * 40) = __floats2half2_rn(v2, v3);
            }
    }
    __syncthreads();
    if (tid == 0) {
        FENCE_ASYNC();
        BULK_S2G(msgs_img + (size_t)tile * 2 * CH_H, sbase + 256 * 4, 20480);
        BULK_COMMIT();
        BULK_WAIT0();
    }
}

// ================= qkv + mma attention =================
// smem (words): inp_b @0(192), mbar @192, A msgs img @256 (5120), B 2x3072 @5376,
//   Q img @11520 (5120), Kfrag @16640 (4096), Vfrag @20736 (4096) | ctx stage @256
#define QI_W  11520
#define KF_W  16640
#define VF_W  20736
#define Q_SM_W 24832
#define QSCALE 0.36067376f   // 0.25 * log2(e)

__global__ void __launch_bounds__(512)
qkvattn_kernel(const __half* __restrict__ msgs_img, const uint2* __restrict__ packQK,
               const float* __restrict__ inp_b, __half* __restrict__ ctx_img)
{
    extern __shared__ float sm[];
    const int tid = threadIdx.x;
    const int tile = blockIdx.x;
    const uint32_t sbase = smem_u32(sm);
    const uint32_t mb0 = sbase + 192 * 4, mb1 = sbase + 194 * 4;

    if (tid < 192) sm[tid] = inp_b[tid];
    if (tid == 0) { MBAR_INIT(mb0, 1); MBAR_INIT(mb1, 1); }
    __syncthreads();

    if (tid == 0) {
        MBAR_EXPECT(mb0, 20480 + 12288);
        BULK_G2S(sbase + 256 * 4, msgs_img + (size_t)tile * 2 * CH_H, 20480, mb0);
        BULK_G2S(sbase + 5376 * 4, (const char*)packQK, 12288, mb0);
        MBAR_EXPECT(mb1, 12288);
        BULK_G2S(sbase + (5376 + 3072) * 4, (const char*)packQK + 12288, 12288, mb1);
    }

    const int lane = tid & 31, w = tid >> 5;
    const int wr = w >> 2, wc = w & 3;
    const int t = lane & 3, g = lane >> 2;
    const int r0 = wr * 32;

    float acc[2][6][4];
#pragma unroll
    for (int mt = 0; mt < 2; mt++)
#pragma unroll
        for (int j = 0; j < 6; j++)
            acc[mt][j][0] = acc[mt][j][1] = acc[mt][j][2] = acc[mt][j][3] = 0.f;

#pragma unroll 1
    for (int cc = 0; cc < 2; cc++) {
        MBAR_WAIT(cc ? mb1 : mb0, 0);
        const uint32_t* sw = (const uint32_t*)(sm + 256 + cc * 2560);
        const uint2*    sB = (const uint2*)(sm + 5376 + cc * 3072);
#pragma unroll
        for (int kk2 = 0; kk2 < 2; kk2++) {
            uint32_t a[2][4];
            LOAD_A(a, sw, r0, kk2, t, g);
#pragma unroll
            for (int j = 0; j < 6; j++) {
                const uint2 bv = sB[(size_t)(kk2 * 24 + wc * 6 + j) * 32 + lane];
#pragma unroll
                for (int mt = 0; mt < 2; mt++) MMA_F16(acc[mt][j], a[mt], bv.x, bv.y);
            }
        }
        __syncthreads();
    }

    // epilogue: scatter Q (scaled) into image layout, K and V into B-fragment order
    {
        __half*   qih = (__half*)(sm + QI_W);
        uint32_t* kfu = (uint32_t*)(sm + KF_W);
        __half*   vfh = (__half*)(sm + VF_W);

        auto kstore = [&](int c, int row, float v0, float v1) {
            const int h = c >> 4, ck = c & 15, part = ck >> 3, td = (ck & 7) >> 1;
            const int lb = row >> 6, na = row & 63, gd = na & 7, jd = na >> 3;
            kfu[(((lb * 4 + h) * 8 + jd) * 2 + part) * 32 + gd * 4 + td] =
                h2u(__floats2half2_rn(v0, v1));
        };
        auto vstore = [&](int c, int row, float val) {
            const int h = c >> 4, dd = c & 15, j2 = dd >> 3, gd = dd & 7;
            const int lb = row >> 6, key = row & 63;
            const int kk = key >> 4, nk = key & 15, part = nk >> 3, td = (nk & 7) >> 1, hi = nk & 1;
            vfh[((((((lb * 4 + h) * 4 + kk) * 2 + j2) * 2 + part) * 32 + gd * 4 + td) << 1) + hi] =
                __float2half_rn(val);
        };

#pragma unroll
        for (int mt = 0; mt < 2; mt++)
#pragma unroll
            for (int j = 0; j < 6; j++) {
                const int n0 = wc * 48 + j * 8 + 2 * t;
                const float b_0 = sm[n0], b_1 = sm[n0 + 1];
                const int rl = r0 + mt * 16 + g;
                const float v0 = acc[mt][j][0] + b_0, v1 = acc[mt][j][1] + b_1;
                const float v2 = acc[mt][j][2] + b_0, v3 = acc[mt][j][3] + b_1;
                if (n0 < 64) {
                    const size_t off = (size_t)(n0 >> 5) * CH_H + (n0 & 31);
                    *(__half2*)(qih + off + (size_t)rl * 40) =
                        __floats2half2_rn(v0 * QSCALE, v1 * QSCALE);
                    *(__half2*)(qih + off + (size_t)(rl + 8) * 40) =
                        __floats2half2_rn(v2 * QSCALE, v3 * QSCALE);
                } else if (n0 < 128) {
                    kstore(n0 - 64, rl, v0, v1);
                    kstore(n0 - 64, rl + 8, v2, v3);
                } else {
                    const int c0 = n0 - 128;
                    vstore(c0, rl, v0);     vstore(c0 + 1, rl, v1);
                    vstore(c0, rl + 8, v2); vstore(c0 + 1, rl + 8, v3);
                }
            }
    }
    __syncthreads();

    // ---- attention on tensor cores: warp = (lb, head, rowhalf) ----
    {
        const int lb = w >> 3, hh = (w >> 1) & 3, rh = w & 1;
        const int rbase = lb * 64 + rh * 32;
        const uint32_t* swQ = (const uint32_t*)(sm + QI_W) + (hh >> 1) * 2560;
        const uint32_t* kfu = (const uint32_t*)(sm + KF_W) + (lb * 4 + hh) * 512;
        const uint32_t* vfu = (const uint32_t*)(sm + VF_W) + (lb * 4 + hh) * 512;

        // S = Qs @ K^T  (K=16, one k-step)
        float s[2][8][4];
#pragma unroll
        for (int mt = 0; mt < 2; mt++)
#pragma unroll
            for (int j = 0; j < 8; j++)
                s[mt][j][0] = s[mt][j][1] = s[mt][j][2] = s[mt][j][3] = 0.f;
        uint32_t aq[2][4];
        LOAD_A(aq, swQ, rbase, (hh & 1), t, g);
#pragma unroll
        for (int j = 0; j < 8; j++) {
            const uint32_t bx = kfu[j * 64 + lane];
            const uint32_t by = kfu[j * 64 + 32 + lane];
#pragma unroll
            for (int mt = 0; mt < 2; mt++) MMA_F16(s[mt][j], aq[mt], bx, by);
        }

        // p = exp2(s) (scale folded into Q); row sums; pack P to fp16 frags
        float rs0[2] = {0.f, 0.f}, rs1[2] = {0.f, 0.f};
        uint32_t ph[2][8][2];
#pragma unroll
        for (int mt = 0; mt < 2; mt++)
#pragma unroll
            for (int j = 0; j < 8; j++) {
                const float p0 = ex2f(s[mt][j][0]);
                const float p1 = ex2f(s[mt][j][1]);
                const float p2 = ex2f(s[mt][j][2]);
                const float p3 = ex2f(s[mt][j][3]);
                rs0[mt] += p0 + p1;
                rs1[mt] += p2 + p3;
                ph[mt][j][0] = h2u(__floats2half2_rn(p0, p1));
                ph[mt][j][1] = h2u(__floats2half2_rn(p2, p3));
            }
#pragma unroll
        for (int mt = 0; mt < 2; mt++) {
            rs0[mt] += __shfl_xor_sync(0xffffffffu, rs0[mt], 1);
            rs0[mt] += __shfl_xor_sync(0xffffffffu, rs0[mt], 2);
            rs1[mt] += __shfl_xor_sync(0xffffffffu, rs1[mt], 1);
            rs1[mt] += __shfl_xor_sync(0xffffffffu, rs1[mt], 2);
        }

        // ctx = P @ V  (K=64: 4 k-steps; N=16: 2 n-tiles)
        float cx[2][2][4];
#pragma unroll
        for (int mt = 0; mt < 2; mt++)
#pragma unroll
            for (int j2 = 0; j2 < 2; j2++)
                cx[mt][j2][0] = cx[mt][j2][1] = cx[mt][j2][2] = cx[mt][j2][3] = 0.f;
#pragma unroll
        for (int kk = 0; kk < 4; kk++) {
#pragma unroll
            for (int j2 = 0; j2 < 2; j2++) {
                const uint32_t bx = vfu[kk * 128 + j2 * 64 + lane];
                const uint32_t by = vfu[kk * 128 + j2 * 64 + 32 + lane];
#pragma unroll
                for (int mt = 0; mt < 2; mt++) {
                    uint32_t ap[4] = { ph[mt][2 * kk][0], ph[mt][2 * kk][1],
                                       ph[mt][2 * kk + 1][0], ph[mt][2 * kk + 1][1] };
                    MMA_F16(cx[mt][j2], ap, bx, by);
                }
            }
        }

        // normalize + store ctx image stage (reuses msgs A region @256)
        __half* cs = (__half*)(sm + 256);
#pragma unroll
        for (int mt = 0; mt < 2; mt++) {
            const float i0 = 1.f / rs0[mt], i1 = 1.f / rs1[mt];
            const int row = rbase + mt * 16 + g;
#pragma unroll
            for (int j2 = 0; j2 < 2; j2++) {
                const int c = hh * 16 + j2 * 8 + 2 * t;
                const size_t off = (size_t)(c >> 5) * CH_H + (c & 31);
                *(__half2*)(cs + off + (size_t)row * 40) =
                    __floats2half2_rn(cx[mt][j2][0] * i0, cx[mt][j2][1] * i0);
                *(__half2*)(cs + off + (size_t)(row + 8) * 40) =
                    __floats2half2_rn(cx[mt][j2][2] * i1, cx[mt][j2][3] * i1);
            }
        }
    }
    __syncthreads();
    if (tid == 0) {
        FENCE_ASYNC();
        BULK_S2G(ctx_img + (size_t)tile * 2 * CH_H, sbase + 256 * 4, 20480);
        BULK_COMMIT();
        BULK_WAIT0();
    }
}

// ================= int1 (unchanged, validated) =================
#define I1_SM_W 25360
__global__ void __launch_bounds__(512)
int1_kernel(const __half* __restrict__ obs_img, const __half* __restrict__ ctx_img,
            const uint2* __restrict__ packI1, const float* __restrict__ bc,
            const float* __restrict__ lng, const float* __restrict__ lnb,
            __half* __restrict__ z_img)
{
    extern __shared__ float sm[];
    const int tid = threadIdx.x;
    const int tile = blockIdx.x;
    const uint32_t sbase = smem_u32(sm);
    const uint32_t mb0 = sbase + 1792 * 4, mb1 = sbase + 1794 * 4;

    if (tid < 256) { sm[tid] = bc[tid]; sm[256 + tid] = lng[tid]; sm[512 + tid] = lnb[tid]; }
    if (tid == 0) { MBAR_INIT(mb0, 1); MBAR_INIT(mb1, 1); }
    __syncthreads();

    if (tid == 0) {
        MBAR_EXPECT(mb0, 40960 + 20480 + 16384);
        BULK_G2S(sbase + 1808 * 4, obs_img + (size_t)tile * 4 * CH_H, 40960, mb0);
        BULK_G2S(sbase + (1808 + 4 * 2560) * 4, ctx_img + (size_t)tile * 2 * CH_H, 20480, mb0);
        BULK_G2S(sbase + 17168 * 4, (const char*)packI1, 16384, mb0);
        MBAR_EXPECT(mb1, 16384);
        BULK_G2S(sbase + (17168 + 4096) * 4, (const char*)packI1 + 16384, 16384, mb1);
    }

    const int lane = tid & 31, w = tid >> 5;
    const int wr = w >> 2, wc = w & 3;
    const int t = lane & 3, g = lane >> 2;
    const int r0 = wr * 32;

    float acc[2][8][4];
#pragma unroll
    for (int mt = 0; mt < 2; mt++)
#pragma unroll
        for (int j = 0; j < 8; j++)
            acc[mt][j][0] = acc[mt][j][1] = acc[mt][j][2] = acc[mt][j][3] = 0.f;

#pragma unroll 1
    for (int cc = 0; cc < 6; cc++) {
        MBAR_WAIT((cc & 1) ? mb1 : mb0, (cc >> 1) & 1);
        const uint32_t* sw = (const uint32_t*)(sm + 1808 + cc * 2560);
        const uint2*    sB = (const uint2*)(sm + 17168 + (cc & 1) * 4096);
#pragma unroll
        for (int kk2 = 0; kk2 < 2; kk2++) {
            uint32_t a[2][4];
            LOAD_A(a, sw, r0, kk2, t, g);
#pragma unroll
            for (int j = 0; j < 8; j++) {
                const uint2 bv = sB[(size_t)(kk2 * 32 + wc * 8 + j) * 32 + lane];
#pragma unroll
                for (int mt = 0; mt < 2; mt++) MMA_F16(acc[mt][j], a[mt], bv.x, bv.y);
            }
        }
        __syncthreads();
        if (cc + 2 < 6 && tid == 0) {
            const uint32_t mb = (cc & 1) ? mb1 : mb0;
            MBAR_EXPECT(mb, 16384);
            BULK_G2S(sbase + (17168 + (cc & 1) * 4096) * 4,
                     (const char*)packI1 + (size_t)(cc + 2) * 16384, 16384, mb);
        }
    }

#pragma unroll
    for (int mt = 0; mt < 2; mt++)
#pragma unroll
        for (int j = 0; j < 8; j++) {
            const int n0 = wc * 64 + j * 8 + 2 * t;
            acc[mt][j][0] += sm[n0]; acc[mt][j][1] += sm[n0 + 1];
            acc[mt][j][2] += sm[n0]; acc[mt][j][3] += sm[n0 + 1];
        }
    float ps[2][2] = {{0,0},{0,0}}, pq[2][2] = {{0,0},{0,0}};
#pragma unroll
    for (int mt = 0; mt < 2; mt++)
#pragma unroll
        for (int j = 0; j < 8; j++) {
            ps[mt][0] += acc[mt][j][0] + acc[mt][j][1];
            pq[mt][0] += acc[mt][j][0] * acc[mt][j][0] + acc[mt][j][1] * acc[mt][j][1];
            ps[mt][1] += acc[mt][j][2] + acc[mt][j][3];
            pq[mt][1] += acc[mt][j][2] * acc[mt][j][2] + acc[mt][j][3] * acc[mt][j][3];
        }
#pragma unroll
    for (int mt = 0; mt < 2; mt++)
#pragma unroll
        for (int h = 0; h < 2; h++) {
            ps[mt][h] += __shfl_xor_sync(0xffffffffu, ps[mt][h], 1);
            ps[mt][h] += __shfl_xor_sync(0xffffffffu, ps[mt][h], 2);
            pq[mt][h] += __shfl_xor_sync(0xffffffffu, pq[mt][h], 1);
            pq[mt][h] += __shfl_xor_sync(0xffffffffu, pq[mt][h], 2);
        }
    if (t == 0) {
#pragma unroll
        for (int mt = 0; mt < 2; mt++)
#pragma unroll
            for (int h = 0; h < 2; h++) {
                const int rl = r0 + mt * 16 + g + 8 * h;
                sm[768 + rl * 4 + wc]       = ps[mt][h];
                sm[768 + 512 + rl * 4 + wc] = pq[mt][h];
            }
    }
    __syncthreads();
    float mu[2][2], rs[2][2];
#pragma unroll
    for (int mt = 0; mt < 2; mt++)
#pragma unroll
        for (int h = 0; h < 2; h++) {
            const int rl = r0 + mt * 16 + g + 8 * h;
            const float s_ = sm[768 + rl * 4] + sm[768 + rl * 4 + 1]
                           + sm[768 + rl * 4 + 2] + sm[768 + rl * 4 + 3];
            const float q_ = sm[1280 + rl * 4] + sm[1280 + rl * 4 + 1]
                           + sm[1280 + rl * 4 + 2] + sm[1280 + rl * 4 + 3];
            const float m_ = s_ * (1.f / 256.f);
            const float v_ = q_ * (1.f / 256.f) - m_ * m_;
            mu[mt][h] = m_;
            rs[mt][h] = rsqrtf(v_ + 1e-5f);
        }
    {
        __half* stg = (__half*)(sm + 1808);
#pragma unroll
        for (int mt = 0; mt < 2; mt++)
#pragma unroll
            for (int j = 0; j < 8; j++) {
                const int n0 = wc * 64 + j * 8 + 2 * t;
                const float g0 = sm[256 + n0], g1 = sm[256 + n0 + 1];
                const float b0 = sm[512 + n0], b1 = sm[512 + n0 + 1];
                const int rl = r0 + mt * 16 + g;
                const size_t off = (size_t)(n0 >> 5) * CH_H + (n0 & 31);
                *(__half2*)(stg + off + (size_t)rl * 40) = __floats2half2_rn(
                    fmaxf((acc[mt][j][0] - mu[mt][0]) * rs[mt][0] * g0 + b0, 0.f),
                    fmaxf((acc[mt][j][1] - mu[mt][0]) * rs[mt][0] * g1 + b1, 0.f));
                *(__half2*)(stg + off + (size_t)(rl + 8) * 40) = __floats2half2_rn(
                    fmaxf((acc[mt][j][2] - mu[mt][1]) * rs[mt][1] * g0 + b0, 0.f),
                    fmaxf((acc[mt][j][3] - mu[mt][1]) * rs[mt][1] * g1 + b1, 0.f));
            }
    }
    __syncthreads();
    if (tid == 0) {
        FENCE_ASYNC();
        BULK_S2G(z_img + (size_t)tile * 8 * CH_H, sbase + 1808 * 4, 81920);
        BULK_COMMIT();
        BULK_WAIT0();
    }
}

// ================= int2 (unchanged, validated) =================
#define I2_SM_W 24832
__global__ void __launch_bounds__(512)
int2_kernel(const __half* __restrict__ z_img, const uint2* __restrict__ packI2,
            const float* __restrict__ ib2, float* __restrict__ outE)
{
    extern __shared__ float sm[];
    const int tid = threadIdx.x;
    const int tile = blockIdx.x;
    const uint32_t sbase = smem_u32(sm);
    const uint32_t mb0 = sbase + 192 * 4, mb1 = sbase + 194 * 4;

    if (tid < 128) sm[tid] = ib2[tid];
    if (tid == 0) { MBAR_INIT(mb0, 1); MBAR_INIT(mb1, 1); }
    __syncthreads();

    if (tid == 0) {
        MBAR_EXPECT(mb0, 81920 + 8192);
        BULK_G2S(sbase + 256 * 4, z_img + (size_t)tile * 8 * CH_H, 81920, mb0);
        BULK_G2S(sbase + 20736 * 4, (const char*)packI2, 8192, mb0);
        MBAR_EXPECT(mb1, 8192);
        BULK_G2S(sbase + (20736 + 2048) * 4, (const char*)packI2 + 8192, 8192, mb1);
    }

    const int lane = tid & 31, w = tid >> 5;
    const int wr = w >> 2, wc = w & 3;
    const int t = lane & 3, g = lane >> 2;
    const int r0 = wr * 32;

    float acc[2][4][4];
#pragma unroll
    for (int mt = 0; mt < 2; mt++)
#pragma unroll
        for (int j = 0; j < 4; j++)
            acc[mt][j][0] = acc[mt][j][1] = acc[mt][j][2] = acc[mt][j][3] = 0.f;

#pragma unroll 1
    for (int cc = 0; cc < 8; cc++) {
        MBAR_WAIT((cc & 1) ? mb1 : mb0, (cc >> 1) & 1);
        const uint32_t* sw = (const uint32_t*)(sm + 256 + cc * 2560);
        const uint2*    sB = (const uint2*)(sm + 20736 + (cc & 1) * 2048);
#pragma unroll
        for (int kk2 = 0; kk2 < 2; kk2++) {
            uint32_t a[2][4];
            LOAD_A(a, sw, r0, kk2, t, g);
#pragma unroll
            for (int j = 0; j < 4; j++) {
                const uint2 bv = sB[(size_t)(kk2 * 16 + wc * 4 + j) * 32 + lane];
#pragma unroll
                for (int mt = 0; mt < 2; mt++) MMA_F16(acc[mt][j], a[mt], bv.x, bv.y);
            }
        }
        __syncthreads();
        if (cc + 2 < 8 && tid == 0) {
            const uint32_t mb = (cc & 1) ? mb1 : mb0;
            MBAR_EXPECT(mb, 8192);
            BULK_G2S(sbase + (20736 + (cc & 1) * 2048) * 4,
                     (const char*)packI2 + (size_t)(cc + 2) * 8192, 8192, mb);
        }
    }
#pragma unroll
    for (int mt = 0; mt < 2; mt++)
#pragma unroll
        for (int j = 0; j < 4; j++) {
            const int n0 = wc * 32 + j * 8 + 2 * t;
            const float b_0 = sm[n0], b_1 = sm[n0 + 1];
            const int rl = r0 + mt * 16 + g;
            *(float2*)(outE + (size_t)(tile * 128 + rl) * 128 + n0) =
                make_float2(acc[mt][j][0] + b_0, acc[mt][j][1] + b_1);
            *(float2*)(outE + (size_t)(tile * 128 + rl + 8) * 128 + n0) =
                make_float2(acc[mt][j][2] + b_0, acc[mt][j][3] + b_1);
        }
}

// ---------------- launch ----------------
extern "C" void kernel_launch(void* const* d_in, const int* in_sizes, int n_in,
                              void* d_out, int out_size)
{
    const float* obs    = (const float*)d_in[0];
    const float* enc_w1 = (const float*)d_in[1];
    const float* enc_b1 = (const float*)d_in[2];
    const float* enc_w2 = (const float*)d_in[3];
    const float* enc_b2 = (const float*)d_in[4];
    const float* inp_w  = (const float*)d_in[5];
    const float* inp_b  = (const float*)d_in[6];
    const float* out_w  = (const float*)d_in[7];
    const float* out_b  = (const float*)d_in[8];
    const float* int_w1 = (const float*)d_in[9];
    const float* int_b1 = (const float*)d_in[10];
    const float* ln_g   = (const float*)d_in[11];
    const float* ln_b   = (const float*)d_in[12];
    const float* int_w2 = (const float*)d_in[13];
    const float* int_b2 = (const float*)d_in[14];

    float* outE = (float*)d_out;
    const size_t esz = (size_t)MTOT * DOBS;
    float* outM = ((size_t)out_size > esz) ? outE + esz : nullptr;

    uint2* p_pack;
    float *p_bc, *p_msgs;
    __half *p_obs_i, *p_msgs_i, *p_ctx_i, *p_z_i;
    cudaGetSymbolAddress((void**)&p_pack,   g_packh);
    cudaGetSymbolAddress((void**)&p_bc,     g_bc);
    cudaGetSymbolAddress((void**)&p_obs_i,  g_obs_img);
    cudaGetSymbolAddress((void**)&p_msgs_i, g_msgs_img);
    cudaGetSymbolAddress((void**)&p_ctx_i,  g_ctx_img);
    cudaGetSymbolAddress((void**)&p_z_i,    g_z_img);
    cudaGetSymbolAddress((void**)&p_msgs,   g_msgs_s);
    float* msgs = outM ? outM : p_msgs;

    cudaFuncSetAttribute(enc12_kernel,   cudaFuncAttributeMaxDynamicSharedMemorySize, E_SM_W * 4);
    cudaFuncSetAttribute(qkvattn_kernel, cudaFuncAttributeMaxDynamicSharedMemorySize, Q_SM_W * 4);
    cudaFuncSetAttribute(int1_kernel,    cudaFuncAttributeMaxDynamicSharedMemorySize, I1_SM_W * 4);
    cudaFuncSetAttribute(int2_kernel,    cudaFuncAttributeMaxDynamicSharedMemorySize, I2_SM_W * 4);

    pack_all<<<(29952 + 255) / 256, 256>>>(enc_w1, enc_w2, inp_w, out_w, out_b,
                                           int_w1, int_b1, int_w2);
    conv_img<<<(MTOT * 16 + 511) / 512, 512>>>(obs, p_obs_i);

    enc12_kernel<<<NTILE, 512, E_SM_W * 4>>>(p_obs_i, p_pack + PH_E1, p_pack + PH_E2,
                                             enc_b1, enc_b2, msgs, p_msgs_i);
    qkvattn_kernel<<<NTILE, 512, Q_SM_W * 4>>>(p_msgs_i, p_pack + PH_QK, inp_b, p_ctx_i);
    int1_kernel<<<NTILE, 512, I1_SM_W * 4>>>(p_obs_i, p_ctx_i, p_pack + PH_I1,
                                             p_bc, ln_g, ln_b, p_z_i);
    int2_kernel<<<NTILE, 512, I2_SM_W * 4>>>(p_z_i, p_pack + PH_I2, int_b2, outE);
}

// round 16
// speedup vs baseline: 1.8198x; 1.4903x over previous
#include <cuda_runtime.h>
#include <cuda_fp16.h>
#include <math.h>
#include <stdint.h>

// ---------------- problem constants ----------------
#define NBATCH 4096
#define NTOK   64
#define MTOT   (NBATCH * NTOK)
#define DOBS   128
#define NTILE  (MTOT / 128)        // 2048
#define CH_H   5120                // halves per image chunk (128 rows x 40)

// ---------------- packed fp16 weight fragments ----------------
#define PH_E1  0
#define PH_E2  4096
#define PH_QK  6144
#define PH_I2  9216
#define PH_I1  17408
#define PH_TOT 29696
__device__ uint2  g_packh[PH_TOT];
__device__ float  g_bc[256];
__device__ __half g_obs_img[(size_t)NTILE * 4 * CH_H];
__device__ __half g_msgs_img[(size_t)NTILE * 2 * CH_H];
__device__ __half g_ctx_img[(size_t)NTILE * 2 * CH_H];
__device__ float  g_msgs_s[(size_t)MTOT * 64];

// ---------------- helpers ----------------
__device__ __forceinline__ uint32_t smem_u32(const void* p) {
    uint32_t a;
    asm("{ .reg .u64 t; cvta.to.shared.u64 t, %1; cvt.u32.u64 %0, t; }" : "=r"(a) : "l"(p));
    return a;
}
#define MBAR_INIT(mb, c) \
    asm volatile("mbarrier.init.shared.b64 [%0], %1;" :: "r"(mb), "r"((uint32_t)(c)) : "memory")
#define MBAR_EXPECT(mb, tx) \
    asm volatile("mbarrier.arrive.expect_tx.shared.b64 _, [%0], %1;" :: "r"(mb), "r"((uint32_t)(tx)) : "memory")
#define BULK_G2S(dst, src, bytes, mb) \
    asm volatile("cp.async.bulk.shared::cta.global.mbarrier::complete_tx::bytes [%0], [%1], %2, [%3];" \
                 :: "r"(dst), "l"(src), "r"((uint32_t)(bytes)), "r"(mb) : "memory")
#define BULK_S2G(gdst, ssrc, bytes) \
    asm volatile("cp.async.bulk.global.shared::cta.bulk_group [%0], [%1], %2;" \
                 :: "l"(gdst), "r"(ssrc), "r"((uint32_t)(bytes)) : "memory")
#define BULK_COMMIT() asm volatile("cp.async.bulk.commit_group;" ::: "memory")
#define BULK_WAIT0()  asm volatile("cp.async.bulk.wait_group 0;" ::: "memory")
#define FENCE_ASYNC() asm volatile("fence.proxy.async.shared::cta;" ::: "memory")
#define MBAR_WAIT(mb, ph) do {                                                      \
    uint32_t _m = (mb), _p = (uint32_t)(ph), _d;                                    \
    asm volatile("{\n\t.reg .pred p;\n\t"                                           \
        "mbarrier.try_wait.parity.acquire.cta.shared::cta.b64 p, [%1], %2;\n\t"     \
        "selp.b32 %0, 1, 0, p;\n\t}" : "=r"(_d) : "r"(_m), "r"(_p) : "memory");     \
    if (!_d) {                                                                      \
        asm volatile("{\n\t.reg .pred P1;\n\t"                                      \
            "WL_%=:\n\t"                                                            \
            "mbarrier.try_wait.parity.acquire.cta.shared::cta.b64 P1, [%0], %1, 0x989680;\n\t" \
            "@P1 bra.uni WD_%=;\n\tbra.uni WL_%=;\n\tWD_%=:\n\t}"                   \
            :: "r"(_m), "r"(_p) : "memory");                                        \
    } } while (0)

#define MMA_F16(acc, a, bx, by)                                                      \
    asm volatile("mma.sync.aligned.m16n8k16.row.col.f32.f16.f16.f32 "                \
                 "{%0,%1,%2,%3}, {%4,%5,%6,%7}, {%8,%9}, {%0,%1,%2,%3};"             \
                 : "+f"((acc)[0]), "+f"((acc)[1]), "+f"((acc)[2]), "+f"((acc)[3])    \
                 : "r"((a)[0]), "r"((a)[1]), "r"((a)[2]), "r"((a)[3]),               \
                   "r"(bx), "r"(by))

__device__ __forceinline__ uint32_t h2u(__half2 h) { return *reinterpret_cast<uint32_t*>(&h); }
__device__ __forceinline__ float ex2f(float x) {
    float r;
    asm("ex2.approx.f32 %0, %1;" : "=f"(r) : "f"(x));
    return r;
}

#define LOAD_A(a, sw, r0, kk2, t, g)                                                 \
    do {                                                                             \
        _Pragma("unroll")                                                            \
        for (int mt = 0; mt < 2; mt++) {                                             \
            const int rb = (r0) + mt * 16 + (g);                                     \
            const int b0 = rb * 20 + (kk2) * 8;                                      \
            const int b1 = (rb + 8) * 20 + (kk2) * 8;                                \
            a[mt][0] = (sw)[b0 + (t)];                                               \
            a[mt][1] = (sw)[b1 + (t)];                                               \
            a[mt][2] = (sw)[b0 + (t) + 4];                                           \
            a[mt][3] = (sw)[b1 + (t) + 4];                                           \
        }                                                                            \
    } while (0)

// ---------------- obs -> fp16 image ----------------
__global__ void conv_img(const float* __restrict__ s, __half* __restrict__ img)
{
    int gid = blockIdx.x * blockDim.x + threadIdx.x;
    if (gid >= MTOT * 16) return;
    const int r = gid >> 4, q = gid & 15;
    float4 v0 = *(const float4*)(s + (size_t)r * 128 + q * 8);
    float4 v1 = *(const float4*)(s + (size_t)r * 128 + q * 8 + 4);
    uint4 o;
    o.x = h2u(__floats2half2_rn(v0.x, v0.y));
    o.y = h2u(__floats2half2_rn(v0.z, v0.w));
    o.z = h2u(__floats2half2_rn(v1.x, v1.y));
    o.w = h2u(__floats2half2_rn(v1.z, v1.w));
    const size_t a = ((size_t)((r >> 7) * 4 + (q >> 2)) * 128 + (r & 127)) * 40 + (q & 3) * 8;
    *(uint4*)(img + a) = o;
}

// ---------------- prep: fold + pack fp16 fragments ----------------
__device__ __forceinline__ float wcomb_elem(int k, int n,
                                            const float* __restrict__ out_w,
                                            const float* __restrict__ int_w1)
{
    if (k < 128) return int_w1[(size_t)k * 256 + n];
    const int c = k - 128;
    float s = 0.f;
#pragma unroll 4
    for (int m = 0; m < 64; m++)
        s = fmaf(out_w[c * 64 + m], int_w1[(size_t)(128 + m) * 256 + n], s);
    return s;
}

__global__ void pack_all(const float* __restrict__ enc_w1, const float* __restrict__ enc_w2,
                         const float* __restrict__ inp_w,  const float* __restrict__ out_w,
                         const float* __restrict__ out_b,  const float* __restrict__ int_w1,
                         const float* __restrict__ int_b1, const float* __restrict__ int_w2)
{
    const int gid = blockIdx.x * blockDim.x + threadIdx.x;
    int p, N = 0;
    const float* W = nullptr;
    uint2* dst = nullptr;
    bool i1 = false;
    if (gid < 4096)        { p = gid;         W = enc_w1; dst = g_packh + PH_E1; N = 128; }
    else if (gid < 6144)   { p = gid - 4096;  W = enc_w2; dst = g_packh + PH_E2; N = 64;  }
    else if (gid < 9216)   { p = gid - 6144;  W = inp_w;  dst = g_packh + PH_QK; N = 192; }
    else if (gid < 17408)  { p = gid - 9216;  W = int_w2; dst = g_packh + PH_I2; N = 128; }
    else if (gid < 29696)  { p = gid - 17408; dst = g_packh + PH_I1; N = 256; i1 = true; }
    else if (gid < 29952) {
        const int n = gid - 29696;
        float s = int_b1[n];
        for (int m = 0; m < 64; m++) s = fmaf(out_b[m], int_w1[(size_t)(128 + m) * 256 + n], s);
        g_bc[n] = s;
        return;
    } else return;

    const int lane = p & 31;
    const int tile = p >> 5;
    const int nt = N >> 3;
    const int j = tile % nt, kk = tile / nt;
    const int t = lane & 3, g = lane >> 2;
    const int k0 = kk * 16, n = j * 8 + g;
    float w0, w1, w2, w3;
    if (i1) {
        w0 = wcomb_elem(k0 + 2 * t,     n, out_w, int_w1);
        w1 = wcomb_elem(k0 + 2 * t + 1, n, out_w, int_w1);
        w2 = wcomb_elem(k0 + 2 * t + 8, n, out_w, int_w1);
        w3 = wcomb_elem(k0 + 2 * t + 9, n, out_w, int_w1);
    } else {
        w0 = W[(size_t)(k0 + 2 * t) * N + n];
        w1 = W[(size_t)(k0 + 2 * t + 1) * N + n];
        w2 = W[(size_t)(k0 + 2 * t + 8) * N + n];
        w3 = W[(size_t)(k0 + 2 * t + 9) * N + n];
    }
    uint2 v;
    v.x = h2u(__floats2half2_rn(w0, w1));
    v.y = h2u(__floats2half2_rn(w2, w3));
    dst[p] = v;
}

// ================= enc1+enc2 fused (round-11 verbatim) =================
#define E_SM_W 24832
__global__ void __launch_bounds__(512)
enc12_kernel(const __half* __restrict__ obs_img,
             const uint2* __restrict__ packE1, const uint2* __restrict__ packE2,
             const float* __restrict__ b1, const float* __restrict__ b2,
             float* __restrict__ msgs32, __half* __restrict__ msgs_img)
{
    extern __shared__ float sm[];
    const int tid = threadIdx.x;
    const int tile = blockIdx.x;
    const uint32_t sbase = smem_u32(sm);
    const uint32_t mb0 = sbase + 192 * 4, mb1 = sbase + 194 * 4;

    if (tid < 128) sm[tid] = b1[tid];
    if (tid < 64)  sm[128 + tid] = b2[tid];
    if (tid == 0) { MBAR_INIT(mb0, 1); MBAR_INIT(mb1, 1); }
    __syncthreads();

    auto bsrc = [&](int cc) -> const char* {
        return (cc < 4) ? (const char*)packE1 + cc * 8192
                        : (const char*)packE2 + (cc - 4) * 4096;
    };
    auto bbytes = [&](int cc) -> uint32_t { return cc < 4 ? 8192u : 4096u; };

    if (tid == 0) {
        MBAR_EXPECT(mb0, 40960 + bbytes(0));
        BULK_G2S(sbase + 256 * 4, obs_img + (size_t)tile * 4 * CH_H, 40960, mb0);
        BULK_G2S(sbase + 20736 * 4, bsrc(0), bbytes(0), mb0);
        MBAR_EXPECT(mb1, bbytes(1));
        BULK_G2S(sbase + (20736 + 2048) * 4, bsrc(1), bbytes(1), mb1);
    }

    const int lane = tid & 31, w = tid >> 5;
    const int wr = w >> 2, wc = w & 3;
    const int t = lane & 3, g = lane >> 2;
    const int r0 = wr * 32;

    float acc1[2][4][4];
#pragma unroll
    for (int mt = 0; mt < 2; mt++)
#pragma unroll
        for (int j = 0; j < 4; j++)
            acc1[mt][j][0] = acc1[mt][j][1] = acc1[mt][j][2] = acc1[mt][j][3] = 0.f;

#pragma unroll 1
    for (int cc = 0; cc < 4; cc++) {
        MBAR_WAIT((cc & 1) ? mb1 : mb0, (cc >> 1) & 1);
        const uint32_t* sw = (const uint32_t*)(sm + 256 + cc * 2560);
        const uint2*    sB = (const uint2*)(sm + 20736 + (cc & 1) * 2048);
#pragma unroll
        for (int kk2 = 0; kk2 < 2; kk2++) {
            uint32_t a[2][4];
            LOAD_A(a, sw, r0, kk2, t, g);
#pragma unroll
            for (int j = 0; j < 4; j++) {
                const uint2 bv = sB[(size_t)(kk2 * 16 + wc * 4 + j) * 32 + lane];
#pragma unroll
                for (int mt = 0; mt < 2; mt++) MMA_F16(acc1[mt][j], a[mt], bv.x, bv.y);
            }
        }
        __syncthreads();
        if (cc + 2 < 8 && tid == 0) {
            const uint32_t mb = (cc & 1) ? mb1 : mb0;
            MBAR_EXPECT(mb, bbytes(cc + 2));
            BULK_G2S(sbase + (20736 + (cc & 1) * 2048) * 4, bsrc(cc + 2), bbytes(cc + 2), mb);
        }
    }
    {
        __half* hA2 = (__half*)(sm + 10496);
#pragma unroll
        for (int mt = 0; mt < 2; mt++)
#pragma unroll
            for (int j = 0; j < 4; j++) {
                const int n0 = wc * 32 + j * 8 + 2 * t;
                const float b_0 = sm[n0], b_1 = sm[n0 + 1];
                const int rl = r0 + mt * 16 + g;
                const size_t off = (size_t)(n0 >> 5) * CH_H + (n0 & 31);
                *(__half2*)(hA2 + off + (size_t)rl * 40) = __floats2half2_rn(
                    fmaxf(acc1[mt][j][0] + b_0, 0.f), fmaxf(acc1[mt][j][1] + b_1, 0.f));
                *(__half2*)(hA2 + off + (size_t)(rl + 8) * 40) = __floats2half2_rn(
                    fmaxf(acc1[mt][j][2] + b_0, 0.f), fmaxf(acc1[mt][j][3] + b_1, 0.f));
            }
    }
    __syncthreads();

    float acc2[2][2][4];
#pragma unroll
    for (int mt = 0; mt < 2; mt++)
#pragma unroll
        for (int j = 0; j < 2; j++)
            acc2[mt][j][0] = acc2[mt][j][1] = acc2[mt][j][2] = acc2[mt][j][3] = 0.f;

#pragma unroll 1
    for (int c2 = 0; c2 < 4; c2++) {
        const int cc = 4 + c2;
        MBAR_WAIT((cc & 1) ? mb1 : mb0, (cc >> 1) & 1);
        const uint32_t* sw = (const uint32_t*)(sm + 10496 + c2 * 2560);
        const uint2*    sB = (const uint2*)(sm + 20736 + (cc & 1) * 2048);
#pragma unroll
        for (int kk2 = 0; kk2 < 2; kk2++) {
            uint32_t a[2][4];
            LOAD_A(a, sw, r0, kk2, t, g);
#pragma unroll
            for (int j = 0; j < 2; j++) {
                const uint2 bv = sB[(size_t)(kk2 * 8 + wc * 2 + j) * 32 + lane];
#pragma unroll
                for (int mt = 0; mt < 2; mt++) MMA_F16(acc2[mt][j], a[mt], bv.x, bv.y);
            }
        }
        __syncthreads();
        if (cc + 2 < 8 && tid == 0) {
            const uint32_t mb = (cc & 1) ? mb1 : mb0;
            MBAR_EXPECT(mb, bbytes(cc + 2));
            BULK_G2S(sbase + (20736 + (cc & 1) * 2048) * 4, bsrc(cc + 2), bbytes(cc + 2), mb);
        }
    }
    {
        __half* stg = (__half*)(sm + 256);
#pragma unroll
        for (int mt = 0; mt < 2; mt++)
#pragma unroll
            for (int j = 0; j < 2; j++) {
                const int n0 = wc * 16 + j * 8 + 2 * t;
                const float b_0 = sm[128 + n0], b_1 = sm[128 + n0 + 1];
                const int rl = r0 + mt * 16 + g;
                const float v0 = acc2[mt][j][0] + b_0, v1 = acc2[mt][j][1] + b_1;
                const float v2 = acc2[mt][j][2] + b_0, v3 = acc2[mt][j][3] + b_1;
                *(float2*)(msgs32 + (size_t)(tile * 128 + rl) * 64 + n0)       = make_float2(v0, v1);
                *(float2*)(msgs32 + (size_t)(tile * 128 + rl + 8) * 64 + n0)   = make_float2(v2, v3);
                const size_t off = (size_t)(n0 >> 5) * CH_H + (n0 & 31);
                *(__half2*)(stg + off + (size_t)rl * 40)       = __floats2half2_rn(v0, v1);
                *(__half2*)(stg + off + (size_t)(rl + 8) * 40) = __floats2half2_rn(v2, v3);
            }
    }
    __syncthreads();
    if (tid == 0) {
        FENCE_ASYNC();
        BULK_S2G(msgs_img + (size_t)tile * 2 * CH_H, sbase + 256 * 4, 20480);
        BULK_COMMIT();
        BULK_WAIT0();
    }
}

// ================= qkv + mma attention (round-11 verbatim) =================
#define QI_W  11520
#define KF_W  16640
#define VF_W  20736
#define Q_SM_W 24832
#define QSCALE 0.36067376f   // 0.25 * log2(e)

__global__ void __launch_bounds__(512)
qkvattn_kernel(const __half* __restrict__ msgs_img, const uint2* __restrict__ packQK,
               const float* __restrict__ inp_b, __half* __restrict__ ctx_img)
{
    extern __shared__ float sm[];
    const int tid = threadIdx.x;
    const int tile = blockIdx.x;
    const uint32_t sbase = smem_u32(sm);
    const uint32_t mb0 = sbase + 192 * 4, mb1 = sbase + 194 * 4;

    if (tid < 192) sm[tid] = inp_b[tid];
    if (tid == 0) { MBAR_INIT(mb0, 1); MBAR_INIT(mb1, 1); }
    __syncthreads();

    if (tid == 0) {
        MBAR_EXPECT(mb0, 20480 + 12288);
        BULK_G2S(sbase + 256 * 4, msgs_img + (size_t)tile * 2 * CH_H, 20480, mb0);
        BULK_G2S(sbase + 5376 * 4, (const char*)packQK, 12288, mb0);
        MBAR_EXPECT(mb1, 12288);
        BULK_G2S(sbase + (5376 + 3072) * 4, (const char*)packQK + 12288, 12288, mb1);
    }

    const int lane = tid & 31, w = tid >> 5;
    const int wr = w >> 2, wc = w & 3;
    const int t = lane & 3, g = lane >> 2;
    const int r0 = wr * 32;

    float acc[2][6][4];
#pragma unroll
    for (int mt = 0; mt < 2; mt++)
#pragma unroll
        for (int j = 0; j < 6; j++)
            acc[mt][j][0] = acc[mt][j][1] = acc[mt][j][2] = acc[mt][j][3] = 0.f;

#pragma unroll 1
    for (int cc = 0; cc < 2; cc++) {
        MBAR_WAIT(cc ? mb1 : mb0, 0);
        const uint32_t* sw = (const uint32_t*)(sm + 256 + cc * 2560);
        const uint2*    sB = (const uint2*)(sm + 5376 + cc * 3072);
#pragma unroll
        for (int kk2 = 0; kk2 < 2; kk2++) {
            uint32_t a[2][4];
            LOAD_A(a, sw, r0, kk2, t, g);
#pragma unroll
            for (int j = 0; j < 6; j++) {
                const uint2 bv = sB[(size_t)(kk2 * 24 + wc * 6 + j) * 32 + lane];
#pragma unroll
                for (int mt = 0; mt < 2; mt++) MMA_F16(acc[mt][j], a[mt], bv.x, bv.y);
            }
        }
        __syncthreads();
    }

    {
        __half*   qih = (__half*)(sm + QI_W);
        uint32_t* kfu = (uint32_t*)(sm + KF_W);
        __half*   vfh = (__half*)(sm + VF_W);

        auto kstore = [&](int c, int row, float v0, float v1) {
            const int h = c >> 4, ck = c & 15, part = ck >> 3, td = (ck & 7) >> 1;
            const int lb = row >> 6, na = row & 63, gd = na & 7, jd = na >> 3;
            kfu[(((lb * 4 + h) * 8 + jd) * 2 + part) * 32 + gd * 4 + td] =
                h2u(__floats2half2_rn(v0, v1));
        };
        auto vstore = [&](int c, int row, float val) {
            const int h = c >> 4, dd = c & 15, j2 = dd >> 3, gd = dd & 7;
            const int lb = row >> 6, key = row & 63;
            const int kk = key >> 4, nk = key & 15, part = nk >> 3, td = (nk & 7) >> 1, hi = nk & 1;
            vfh[((((((lb * 4 + h) * 4 + kk) * 2 + j2) * 2 + part) * 32 + gd * 4 + td) << 1) + hi] =
                __float2half_rn(val);
        };

#pragma unroll
        for (int mt = 0; mt < 2; mt++)
#pragma unroll
            for (int j = 0; j < 6; j++) {
                const int n0 = wc * 48 + j * 8 + 2 * t;
                const float b_0 = sm[n0], b_1 = sm[n0 + 1];
                const int rl = r0 + mt * 16 + g;
                const float v0 = acc[mt][j][0] + b_0, v1 = acc[mt][j][1] + b_1;
                const float v2 = acc[mt][j][2] + b_0, v3 = acc[mt][j][3] + b_1;
                if (n0 < 64) {
                    const size_t off = (size_t)(n0 >> 5) * CH_H + (n0 & 31);
                    *(__half2*)(qih + off + (size_t)rl * 40) =
                        __floats2half2_rn(v0 * QSCALE, v1 * QSCALE);
                    *(__half2*)(qih + off + (size_t)(rl + 8) * 40) =
                        __floats2half2_rn(v2 * QSCALE, v3 * QSCALE);
                } else if (n0 < 128) {
                    kstore(n0 - 64, rl, v0, v1);
                    kstore(n0 - 64, rl + 8, v2, v3);
                } else {
                    const int c0 = n0 - 128;
                    vstore(c0, rl, v0);     vstore(c0 + 1, rl, v1);
                    vstore(c0, rl + 8, v2); vstore(c0 + 1, rl + 8, v3);
                }
            }
    }
    __syncthreads();

    {
        const int lb = w >> 3, hh = (w >> 1) & 3, rh = w & 1;
        const int rbase = lb * 64 + rh * 32;
        const uint32_t* swQ = (const uint32_t*)(sm + QI_W) + (hh >> 1) * 2560;
        const uint32_t* kfu = (const uint32_t*)(sm + KF_W) + (lb * 4 + hh) * 512;
        const uint32_t* vfu = (const uint32_t*)(sm + VF_W) + (lb * 4 + hh) * 512;

        float s[2][8][4];
#pragma unroll
        for (int mt = 0; mt < 2; mt++)
#pragma unroll
            for (int j = 0; j < 8; j++)
                s[mt][j][0] = s[mt][j][1] = s[mt][j][2] = s[mt][j][3] = 0.f;
        uint32_t aq[2][4];
        LOAD_A(aq, swQ, rbase, (hh & 1), t, g);
#pragma unroll
        for (int j = 0; j < 8; j++) {
            const uint32_t bx = kfu[j * 64 + lane];
            const uint32_t by = kfu[j * 64 + 32 + lane];
#pragma unroll
            for (int mt = 0; mt < 2; mt++) MMA_F16(s[mt][j], aq[mt], bx, by);
        }

        float rs0[2] = {0.f, 0.f}, rs1[2] = {0.f, 0.f};
        uint32_t ph[2][8][2];
#pragma unroll
        for (int mt = 0; mt < 2; mt++)
#pragma unroll
            for (int j = 0; j < 8; j++) {
                const float p0 = ex2f(s[mt][j][0]);
                const float p1 = ex2f(s[mt][j][1]);
                const float p2 = ex2f(s[mt][j][2]);
                const float p3 = ex2f(s[mt][j][3]);
                rs0[mt] += p0 + p1;
                rs1[mt] += p2 + p3;
                ph[mt][j][0] = h2u(__floats2half2_rn(p0, p1));
                ph[mt][j][1] = h2u(__floats2half2_rn(p2, p3));
            }
#pragma unroll
        for (int mt = 0; mt < 2; mt++) {
            rs0[mt] += __shfl_xor_sync(0xffffffffu, rs0[mt], 1);
            rs0[mt] += __shfl_xor_sync(0xffffffffu, rs0[mt], 2);
            rs1[mt] += __shfl_xor_sync(0xffffffffu, rs1[mt], 1);
            rs1[mt] += __shfl_xor_sync(0xffffffffu, rs1[mt], 2);
        }

        float cx[2][2][4];
#pragma unroll
        for (int mt = 0; mt < 2; mt++)
#pragma unroll
            for (int j2 = 0; j2 < 2; j2++)
                cx[mt][j2][0] = cx[mt][j2][1] = cx[mt][j2][2] = cx[mt][j2][3] = 0.f;
#pragma unroll
        for (int kk = 0; kk < 4; kk++) {
#pragma unroll
            for (int j2 = 0; j2 < 2; j2++) {
                const uint32_t bx = vfu[kk * 128 + j2 * 64 + lane];
                const uint32_t by = vfu[kk * 128 + j2 * 64 + 32 + lane];
#pragma unroll
                for (int mt = 0; mt < 2; mt++) {
                    uint32_t ap[4] = { ph[mt][2 * kk][0], ph[mt][2 * kk][1],
                                       ph[mt][2 * kk + 1][0], ph[mt][2 * kk + 1][1] };
                    MMA_F16(cx[mt][j2], ap, bx, by);
                }
            }
        }

        __half* cs = (__half*)(sm + 256);
#pragma unroll
        for (int mt = 0; mt < 2; mt++) {
            const float i0 = 1.f / rs0[mt], i1 = 1.f / rs1[mt];
            const int row = rbase + mt * 16 + g;
#pragma unroll
            for (int j2 = 0; j2 < 2; j2++) {
                const int c = hh * 16 + j2 * 8 + 2 * t;
                const size_t off = (size_t)(c >> 5) * CH_H + (c & 31);
                *(__half2*)(cs + off + (size_t)row * 40) =
                    __floats2half2_rn(cx[mt][j2][0] * i0, cx[mt][j2][1] * i0);
                *(__half2*)(cs + off + (size_t)(row + 8) * 40) =
                    __floats2half2_rn(cx[mt][j2][2] * i1, cx[mt][j2][3] * i1);
            }
        }
    }
    __syncthreads();
    if (tid == 0) {
        FENCE_ASYNC();
        BULK_S2G(ctx_img + (size_t)tile * 2 * CH_H, sbase + 256 * 4, 20480);
        BULK_COMMIT();
        BULK_WAIT0();
    }
}

// ================= back: int1(+LN) + int2, z in smem, NO barrier reuse =================
// word layout (no aliasing):
//   bc @0(256), lng @256, lnb @512, ib2 @768(128), scratch @896(1024),
//   mbar @1920 (mb0,mb1,mb2,mb3 at 1920/1922/1924/1926),
//   A imgs @2048 (obs 4x2560 + ctx 2x2560 = 15360),
//   int1 B S0 @17408(4096), S1 @21504(4096),
//   z @25600 (8x2560 = 20480),
//   int2 B T0 @46080(2048), T1 @48128(2048)
#define BK_AO  2048
#define BK_S0  17408
#define BK_S1  21504
#define BK_Z   25600
#define BK_T0  46080
#define BK_T1  48128
#define BK_SM_W 50176   // 200704 bytes
__global__ void __launch_bounds__(512)
back_kernel(const __half* __restrict__ obs_img, const __half* __restrict__ ctx_img,
            const uint2* __restrict__ packI1, const uint2* __restrict__ packI2,
            const float* __restrict__ bc, const float* __restrict__ lng,
            const float* __restrict__ lnb, const float* __restrict__ ib2,
            float* __restrict__ outE)
{
    extern __shared__ float sm[];
    const int tid = threadIdx.x;
    const int tile = blockIdx.x;
    const uint32_t sbase = smem_u32(sm);
    const uint32_t mb0 = sbase + 1920 * 4, mb1 = sbase + 1922 * 4;
    const uint32_t mb2 = sbase + 1924 * 4, mb3 = sbase + 1926 * 4;

    if (tid < 256) { sm[tid] = bc[tid]; sm[256 + tid] = lng[tid]; sm[512 + tid] = lnb[tid]; }
    if (tid < 128) sm[768 + tid] = ib2[tid];
    if (tid == 0) { MBAR_INIT(mb0, 1); MBAR_INIT(mb1, 1); MBAR_INIT(mb2, 1); MBAR_INIT(mb3, 1); }
    __syncthreads();

    if (tid == 0) {
        MBAR_EXPECT(mb0, 40960 + 20480 + 16384);
        BULK_G2S(sbase + BK_AO * 4, obs_img + (size_t)tile * 4 * CH_H, 40960, mb0);
        BULK_G2S(sbase + (BK_AO + 4 * 2560) * 4, ctx_img + (size_t)tile * 2 * CH_H, 20480, mb0);
        BULK_G2S(sbase + BK_S0 * 4, (const char*)packI1, 16384, mb0);
        MBAR_EXPECT(mb1, 16384);
        BULK_G2S(sbase + BK_S1 * 4, (const char*)packI1 + 16384, 16384, mb1);
    }

    const int lane = tid & 31, w = tid >> 5;
    const int wr = w >> 2, wc = w & 3;
    const int t = lane & 3, g = lane >> 2;
    const int r0 = wr * 32;

    // ---- int1 mainloop: N=256, NT=8, 6 chunks (mb0/mb1, validated pattern) ----
    float acc[2][8][4];
#pragma unroll
    for (int mt = 0; mt < 2; mt++)
#pragma unroll
        for (int j = 0; j < 8; j++)
            acc[mt][j][0] = acc[mt][j][1] = acc[mt][j][2] = acc[mt][j][3] = 0.f;

#pragma unroll 1
    for (int cc = 0; cc < 6; cc++) {
        MBAR_WAIT((cc & 1) ? mb1 : mb0, (cc >> 1) & 1);
        const uint32_t* sw = (const uint32_t*)(sm + BK_AO + cc * 2560);
        const uint2*    sB = (const uint2*)(sm + ((cc & 1) ? BK_S1 : BK_S0));
#pragma unroll
        for (int kk2 = 0; kk2 < 2; kk2++) {
            uint32_t a[2][4];
            LOAD_A(a, sw, r0, kk2, t, g);
#pragma unroll
            for (int j = 0; j < 8; j++) {
                const uint2 bv = sB[(size_t)(kk2 * 32 + wc * 8 + j) * 32 + lane];
#pragma unroll
                for (int mt = 0; mt < 2; mt++) MMA_F16(acc[mt][j], a[mt], bv.x, bv.y);
            }
        }
        __syncthreads();
        if (cc + 2 < 6 && tid == 0) {
            const uint32_t mb = (cc & 1) ? mb1 : mb0;
            MBAR_EXPECT(mb, 16384);
            BULK_G2S(sbase + ((cc & 1) ? BK_S1 : BK_S0) * 4,
                     (const char*)packI1 + (size_t)(cc + 2) * 16384, 16384, mb);
        }
    }
    // prefetch int2 B chunks 0,1 on FRESH barriers mb2/mb3 (first wait = parity 0)
    if (tid == 0) {
        MBAR_EXPECT(mb2, 8192);
        BULK_G2S(sbase + BK_T0 * 4, (const char*)packI2, 8192, mb2);
        MBAR_EXPECT(mb3, 8192);
        BULK_G2S(sbase + BK_T1 * 4, (const char*)packI2 + 8192, 8192, mb3);
    }

    // ---- int1 epilogue: bias + LayerNorm + relu -> z in smem ----
#pragma unroll
    for (int mt = 0; mt < 2; mt++)
#pragma unroll
        for (int j = 0; j < 8; j++) {
            const int n0 = wc * 64 + j * 8 + 2 * t;
            acc[mt][j][0] += sm[n0]; acc[mt][j][1] += sm[n0 + 1];
            acc[mt][j][2] += sm[n0]; acc[mt][j][3] += sm[n0 + 1];
        }
    float ps[2][2] = {{0,0},{0,0}}, pq[2][2] = {{0,0},{0,0}};
#pragma unroll
    for (int mt = 0; mt < 2; mt++)
#pragma unroll
        for (int j = 0; j < 8; j++) {
            ps[mt][0] += acc[mt][j][0] + acc[mt][j][1];
            pq[mt][0] += acc[mt][j][0] * acc[mt][j][0] + acc[mt][j][1] * acc[mt][j][1];
            ps[mt][1] += acc[mt][j][2] + acc[mt][j][3];
            pq[mt][1] += acc[mt][j][2] * acc[mt][j][2] + acc[mt][j][3] * acc[mt][j][3];
        }
#pragma unroll
    for (int mt = 0; mt < 2; mt++)
#pragma unroll
        for (int h = 0; h < 2; h++) {
            ps[mt][h] += __shfl_xor_sync(0xffffffffu, ps[mt][h], 1);
            ps[mt][h] += __shfl_xor_sync(0xffffffffu, ps[mt][h], 2);
            pq[mt][h] += __shfl_xor_sync(0xffffffffu, pq[mt][h], 1);
            pq[mt][h] += __shfl_xor_sync(0xffffffffu, pq[mt][h], 2);
        }
    if (t == 0) {
#pragma unroll
        for (int mt = 0; mt < 2; mt++)
#pragma unroll
            for (int h = 0; h < 2; h++) {
                const int rl = r0 + mt * 16 + g + 8 * h;
                sm[896 + rl * 4 + wc]       = ps[mt][h];
                sm[896 + 512 + rl * 4 + wc] = pq[mt][h];
            }
    }
    __syncthreads();
    float mu[2][2], rs[2][2];
#pragma unroll
    for (int mt = 0; mt < 2; mt++)
#pragma unroll
        for (int h = 0; h < 2; h++) {
            const int rl = r0 + mt * 16 + g + 8 * h;
            const float s_ = sm[896 + rl * 4] + sm[896 + rl * 4 + 1]
                           + sm[896 + rl * 4 + 2] + sm[896 + rl * 4 + 3];
            const float q_ = sm[1408 + rl * 4] + sm[1408 + rl * 4 + 1]
                           + sm[1408 + rl * 4 + 2] + sm[1408 + rl * 4 + 3];
            const float m_ = s_ * (1.f / 256.f);
            const float v_ = q_ * (1.f / 256.f) - m_ * m_;
            mu[mt][h] = m_;
            rs[mt][h] = rsqrtf(v_ + 1e-5f);
        }
    // z store to its OWN region (no aliasing with scratch/A/B)
    {
#pragma unroll
        for (int mt = 0; mt < 2; mt++)
#pragma unroll
            for (int j = 0; j < 8; j++) {
                const int n0 = wc * 64 + j * 8 + 2 * t;
                __half* stg = (__half*)(sm + BK_Z + (n0 >> 5) * 2560);
                const float g0 = sm[256 + n0], g1 = sm[256 + n0 + 1];
                const float b0 = sm[512 + n0], b1 = sm[512 + n0 + 1];
                const int rl = r0 + mt * 16 + g;
                const size_t off = (size_t)(n0 & 31);
                *(__half2*)(stg + off + (size_t)rl * 40) = __floats2half2_rn(
                    fmaxf((acc[mt][j][0] - mu[mt][0]) * rs[mt][0] * g0 + b0, 0.f),
                    fmaxf((acc[mt][j][1] - mu[mt][0]) * rs[mt][0] * g1 + b1, 0.f));
                *(__half2*)(stg + off + (size_t)(rl + 8) * 40) = __floats2half2_rn(
                    fmaxf((acc[mt][j][2] - mu[mt][1]) * rs[mt][1] * g0 + b0, 0.f),
                    fmaxf((acc[mt][j][3] - mu[mt][1]) * rs[mt][1] * g1 + b1, 0.f));
            }
    }
    __syncthreads();

    // ---- int2 mainloop: N=128, NT=4, 8 chunks; fresh mb2/mb3, parity (c2>>1)&1 ----
    float acc2[2][4][4];
#pragma unroll
    for (int mt = 0; mt < 2; mt++)
#pragma unroll
        for (int j = 0; j < 4; j++)
            acc2[mt][j][0] = acc2[mt][j][1] = acc2[mt][j][2] = acc2[mt][j][3] = 0.f;

#pragma unroll 1
    for (int c2 = 0; c2 < 8; c2++) {
        MBAR_WAIT((c2 & 1) ? mb3 : mb2, (c2 >> 1) & 1);
        const uint32_t* sw = (const uint32_t*)(sm + BK_Z + c2 * 2560);
        const uint2*    sB = (const uint2*)(sm + ((c2 & 1) ? BK_T1 : BK_T0));
#pragma unroll
        for (int kk2 = 0; kk2 < 2; kk2++) {
            uint32_t a[2][4];
            LOAD_A(a, sw, r0, kk2, t, g);
#pragma unroll
            for (int j = 0; j < 4; j++) {
                const uint2 bv = sB[(size_t)(kk2 * 16 + wc * 4 + j) * 32 + lane];
#pragma unroll
                for (int mt = 0; mt < 2; mt++) MMA_F16(acc2[mt][j], a[mt], bv.x, bv.y);
            }
        }
        __syncthreads();
        if (c2 + 2 < 8 && tid == 0) {
            const uint32_t mb = (c2 & 1) ? mb3 : mb2;
            MBAR_EXPECT(mb, 8192);
            BULK_G2S(sbase + ((c2 & 1) ? BK_T1 : BK_T0) * 4,
                     (const char*)packI2 + (size_t)(c2 + 2) * 8192, 8192, mb);
        }
    }
#pragma unroll
    for (int mt = 0; mt < 2; mt++)
#pragma unroll
        for (int j = 0; j < 4; j++) {
            const int n0 = wc * 32 + j * 8 + 2 * t;
            const float b_0 = sm[768 + n0], b_1 = sm[768 + n0 + 1];
            const int rl = r0 + mt * 16 + g;
            *(float2*)(outE + (size_t)(tile * 128 + rl) * 128 + n0) =
                make_float2(acc2[mt][j][0] + b_0, acc2[mt][j][1] + b_1);
            *(float2*)(outE + (size_t)(tile * 128 + rl + 8) * 128 + n0) =
                make_float2(acc2[mt][j][2] + b_0, acc2[mt][j][3] + b_1);
        }
}

// ---------------- launch ----------------
extern "C" void kernel_launch(void* const* d_in, const int* in_sizes, int n_in,
                              void* d_out, int out_size)
{
    const float* obs    = (const float*)d_in[0];
    const float* enc_w1 = (const float*)d_in[1];
    const float* enc_b1 = (const float*)d_in[2];
    const float* enc_w2 = (const float*)d_in[3];
    const float* enc_b2 = (const float*)d_in[4];
    const float* inp_w  = (const float*)d_in[5];
    const float* inp_b  = (const float*)d_in[6];
    const float* out_w  = (const float*)d_in[7];
    const float* out_b  = (const float*)d_in[8];
    const float* int_w1 = (const float*)d_in[9];
    const float* int_b1 = (const float*)d_in[10];
    const float* ln_g   = (const float*)d_in[11];
    const float* ln_b   = (const float*)d_in[12];
    const float* int_w2 = (const float*)d_in[13];
    const float* int_b2 = (const float*)d_in[14];

    float* outE = (float*)d_out;
    const size_t esz = (size_t)MTOT * DOBS;
    float* outM = ((size_t)out_size > esz) ? outE + esz : nullptr;

    uint2* p_pack;
    float *p_bc, *p_msgs;
    __half *p_obs_i, *p_msgs_i, *p_ctx_i;
    cudaGetSymbolAddress((void**)&p_pack,   g_packh);
    cudaGetSymbolAddress((void**)&p_bc,     g_bc);
    cudaGetSymbolAddress((void**)&p_obs_i,  g_obs_img);
    cudaGetSymbolAddress((void**)&p_msgs_i, g_msgs_img);
    cudaGetSymbolAddress((void**)&p_ctx_i,  g_ctx_img);
    cudaGetSymbolAddress((void**)&p_msgs,   g_msgs_s);
    float* msgs = outM ? outM : p_msgs;

    cudaFuncSetAttribute(enc12_kernel,   cudaFuncAttributeMaxDynamicSharedMemorySize, E_SM_W * 4);
    cudaFuncSetAttribute(qkvattn_kernel, cudaFuncAttributeMaxDynamicSharedMemorySize, Q_SM_W * 4);
    cudaFuncSetAttribute(back_kernel,    cudaFuncAttributeMaxDynamicSharedMemorySize, BK_SM_W * 4);

    pack_all<<<(29952 + 255) / 256, 256>>>(enc_w1, enc_w2, inp_w, out_w, out_b,
                                           int_w1, int_b1, int_w2);
    conv_img<<<(MTOT * 16 + 511) / 512, 512>>>(obs, p_obs_i);

    enc12_kernel<<<NTILE, 512, E_SM_W * 4>>>(p_obs_i, p_pack + PH_E1, p_pack + PH_E2,
                                             enc_b1, enc_b2, msgs, p_msgs_i);
    qkvattn_kernel<<<NTILE, 512, Q_SM_W * 4>>>(p_msgs_i, p_pack + PH_QK, inp_b, p_ctx_i);
    back_kernel<<<NTILE, 512, BK_SM_W * 4>>>(p_obs_i, p_ctx_i, p_pack + PH_I1, p_pack + PH_I2,
                                             p_bc, ln_g, ln_b, int_b2, outE);
}